// round 2
// baseline (speedup 1.0000x reference)
#include <cuda_runtime.h>
#include <cstdint>

#define B_SZ 2
#define S_LEN 2048
#define HID_C 2048
#define N_HEADS 16
#define HEAD_D 128
#define M_ROWS (B_SZ * S_LEN)   /* 4096 */
#define KV_C 256

#define SOFTMAX_SCALE 0.08838834764831845f  /* 1/sqrt(128) */

// Scratch (allocation-free rule: device globals)
__device__ float g_Q[(size_t)M_ROWS * HID_C];    // 33.5 MB
__device__ float g_KV[(size_t)M_ROWS * KV_C];    //  4.2 MB
__device__ float g_attn[(size_t)M_ROWS * HID_C]; // 33.5 MB

// ---------------------------------------------------------------------------
// SGEMM: C[M,N] = A[M,K] @ B[K,N] + bias[N]; row-major; M%128==0, N%128==0
// (N==256 ok too), K%8==0. 128x128 block, 8x8 micro, double-buffered smem.
// ---------------------------------------------------------------------------
__global__ __launch_bounds__(256, 2)
void sgemm_bias_kernel(const float* __restrict__ A, const float* __restrict__ Bm,
                       const float* __restrict__ bias, float* __restrict__ C,
                       int M, int N, int K)
{
    __shared__ float As[2][8][128];
    __shared__ float Bs[2][8][128];
    const int tid = threadIdx.x;
    const int tx = tid & 15;
    const int ty = tid >> 4;
    const int bm = blockIdx.y * 128;
    const int bn = blockIdx.x * 128;

    const int arow = tid >> 1;          // 0..127
    const int acol = (tid & 1) * 4;     // 0 or 4
    const int brow = tid >> 5;          // 0..7
    const int bcol = (tid & 31) * 4;    // 0..124

    const float* Ap = A + (size_t)(bm + arow) * K + acol;
    const float* Bp = Bm + (size_t)brow * N + bn + bcol;

    float acc[8][8];
#pragma unroll
    for (int i = 0; i < 8; i++)
#pragma unroll
        for (int j = 0; j < 8; j++) acc[i][j] = 0.f;

    float4 a4 = *(const float4*)Ap;
    float4 b4 = *(const float4*)Bp;
    As[0][acol + 0][arow] = a4.x;
    As[0][acol + 1][arow] = a4.y;
    As[0][acol + 2][arow] = a4.z;
    As[0][acol + 3][arow] = a4.w;
    *(float4*)&Bs[0][brow][bcol] = b4;
    __syncthreads();

    const int ntiles = K >> 3;
    for (int t = 0; t < ntiles; t++) {
        const int cur = t & 1;
        if (t + 1 < ntiles) {
            a4 = *(const float4*)(Ap + (size_t)(t + 1) * 8);
            b4 = *(const float4*)(Bp + (size_t)(t + 1) * 8 * N);
        }
#pragma unroll
        for (int k = 0; k < 8; k++) {
            float ar[8], br[8];
            *(float4*)&ar[0] = *(const float4*)&As[cur][k][ty * 8];
            *(float4*)&ar[4] = *(const float4*)&As[cur][k][ty * 8 + 4];
            *(float4*)&br[0] = *(const float4*)&Bs[cur][k][tx * 8];
            *(float4*)&br[4] = *(const float4*)&Bs[cur][k][tx * 8 + 4];
#pragma unroll
            for (int i = 0; i < 8; i++)
#pragma unroll
                for (int j = 0; j < 8; j++)
                    acc[i][j] = fmaf(ar[i], br[j], acc[i][j]);
        }
        if (t + 1 < ntiles) {
            const int nxt = cur ^ 1;
            As[nxt][acol + 0][arow] = a4.x;
            As[nxt][acol + 1][arow] = a4.y;
            As[nxt][acol + 2][arow] = a4.z;
            As[nxt][acol + 3][arow] = a4.w;
            *(float4*)&Bs[nxt][brow][bcol] = b4;
            __syncthreads();
        }
    }

#pragma unroll
    for (int i = 0; i < 8; i++) {
        float* Cp = C + (size_t)(bm + ty * 8 + i) * N + bn + tx * 8;
#pragma unroll
        for (int j = 0; j < 8; j += 4) {
            float4 r;
            r.x = acc[i][j + 0] + bias[bn + tx * 8 + j + 0];
            r.y = acc[i][j + 1] + bias[bn + tx * 8 + j + 1];
            r.z = acc[i][j + 2] + bias[bn + tx * 8 + j + 2];
            r.w = acc[i][j + 3] + bias[bn + tx * 8 + j + 3];
            *(float4*)(Cp + j) = r;
        }
    }
}

// ---------------------------------------------------------------------------
// Flash attention (causal, fp32). One block = 64 q-rows x one head x one batch.
// Q/K stored transposed [d][64] with XOR swizzle (chunk ^ (d>>2)&15) so both
// the transpose STS and the inner-loop float4 LDS are (near-)conflict-free.
// Online softmax; P staged through smem; O in registers (4 rows x 8 d cols).
// ---------------------------------------------------------------------------
#define FA_BM 64
#define FA_BN 64
#define QS_OFF 0
#define KS_OFF (128 * 64)
#define VS_OFF (2 * 128 * 64)
#define PS_OFF (2 * 128 * 64 + 64 * 128)
#define FA_SMEM_FLOATS (3 * 128 * 64 + 64 * 65)   /* 28736 floats = 114944 B */

__global__ __launch_bounds__(256, 2)
void flash_attn_kernel()
{
    extern __shared__ float smf[];
    float* Qs = smf + QS_OFF;   // [128][64] swizzled transposed
    float* Ks = smf + KS_OFF;   // [128][64] swizzled transposed
    float* Vs = smf + VS_OFF;   // [64][128]
    float* Ps = smf + PS_OFF;   // [64][65]

    const int tid = threadIdx.x;
    const int tx = tid & 15;
    const int ty = tid >> 4;
    const int qt = (int)gridDim.x - 1 - (int)blockIdx.x;  // heavy blocks first
    const int h = blockIdx.y;
    const int b = blockIdx.z;
    const int m0 = qt * FA_BM;

    const size_t qrow0 = (size_t)(b * S_LEN + m0);

    // Load Q tile transposed+swizzled. element (d, r) -> d*64 + ((r>>2)^((d>>2)&15))*4 + (r&3)
#pragma unroll
    for (int it = 0; it < 8; it++) {
        int i = tid + it * 256;
        int r = i >> 5;
        int c4 = (i & 31) * 4;
        float4 q4 = *(const float4*)&g_Q[(qrow0 + r) * HID_C + h * HEAD_D + c4];
        int swo = (((r >> 2) ^ ((c4 >> 2) & 15)) << 2) + (r & 3);
        Qs[(c4 + 0) * 64 + swo] = q4.x;
        Qs[(c4 + 1) * 64 + swo] = q4.y;
        Qs[(c4 + 2) * 64 + swo] = q4.z;
        Qs[(c4 + 3) * 64 + swo] = q4.w;
    }

    float o[4][8];
#pragma unroll
    for (int i = 0; i < 4; i++)
#pragma unroll
        for (int j = 0; j < 8; j++) o[i][j] = 0.f;
    float mrow[4] = {-1e30f, -1e30f, -1e30f, -1e30f};
    float lrow[4] = {0.f, 0.f, 0.f, 0.f};

    const size_t kvrow0 = (size_t)b * S_LEN;

    for (int t = 0; t <= qt; t++) {
        const int n0 = t * FA_BN;
        __syncthreads();  // prev PV reads done (and Q writes visible on t==0)
        // Load K (transposed+swizzled) and V tiles
#pragma unroll
        for (int it = 0; it < 8; it++) {
            int i = tid + it * 256;
            int r = i >> 5;
            int c4 = (i & 31) * 4;
            const float* kvp = &g_KV[(kvrow0 + n0 + r) * KV_C];
            float4 k4 = *(const float4*)(kvp + c4);
            int swo = (((r >> 2) ^ ((c4 >> 2) & 15)) << 2) + (r & 3);
            Ks[(c4 + 0) * 64 + swo] = k4.x;
            Ks[(c4 + 1) * 64 + swo] = k4.y;
            Ks[(c4 + 2) * 64 + swo] = k4.z;
            Ks[(c4 + 3) * 64 + swo] = k4.w;
            float4 v4 = *(const float4*)(kvp + HEAD_D + c4);
            *(float4*)&Vs[r * 128 + c4] = v4;
        }
        __syncthreads();

        // S = Q K^T (4x4 per thread over 64x64 tile)
        float acc[4][4];
#pragma unroll
        for (int i = 0; i < 4; i++)
#pragma unroll
            for (int j = 0; j < 4; j++) acc[i][j] = 0.f;

#pragma unroll 2
        for (int d4 = 0; d4 < 32; d4++) {
            const int sw = d4 & 15;
            const float* qrow = &Qs[d4 * 4 * 64];
            const float* krow = &Ks[d4 * 4 * 64];
            const int aoff = (ty ^ sw) << 2;
            const int boff = (tx ^ sw) << 2;
#pragma unroll
            for (int dd = 0; dd < 4; dd++) {
                float4 a = *(const float4*)&qrow[dd * 64 + aoff];
                float4 bk = *(const float4*)&krow[dd * 64 + boff];
                acc[0][0] = fmaf(a.x, bk.x, acc[0][0]);
                acc[0][1] = fmaf(a.x, bk.y, acc[0][1]);
                acc[0][2] = fmaf(a.x, bk.z, acc[0][2]);
                acc[0][3] = fmaf(a.x, bk.w, acc[0][3]);
                acc[1][0] = fmaf(a.y, bk.x, acc[1][0]);
                acc[1][1] = fmaf(a.y, bk.y, acc[1][1]);
                acc[1][2] = fmaf(a.y, bk.z, acc[1][2]);
                acc[1][3] = fmaf(a.y, bk.w, acc[1][3]);
                acc[2][0] = fmaf(a.z, bk.x, acc[2][0]);
                acc[2][1] = fmaf(a.z, bk.y, acc[2][1]);
                acc[2][2] = fmaf(a.z, bk.z, acc[2][2]);
                acc[2][3] = fmaf(a.z, bk.w, acc[2][3]);
                acc[3][0] = fmaf(a.w, bk.x, acc[3][0]);
                acc[3][1] = fmaf(a.w, bk.y, acc[3][1]);
                acc[3][2] = fmaf(a.w, bk.z, acc[3][2]);
                acc[3][3] = fmaf(a.w, bk.w, acc[3][3]);
            }
        }

        // scale + causal mask + online softmax (row owned by 16 tx threads)
        const bool diag = (t == qt);
#pragma unroll
        for (int i = 0; i < 4; i++) {
#pragma unroll
            for (int j = 0; j < 4; j++) {
                float s = acc[i][j] * SOFTMAX_SCALE;
                if (diag && (tx * 4 + j > ty * 4 + i)) s = -1e30f;
                acc[i][j] = s;
            }
            float tm = fmaxf(fmaxf(acc[i][0], acc[i][1]), fmaxf(acc[i][2], acc[i][3]));
            tm = fmaxf(tm, __shfl_xor_sync(0xffffffffu, tm, 1));
            tm = fmaxf(tm, __shfl_xor_sync(0xffffffffu, tm, 2));
            tm = fmaxf(tm, __shfl_xor_sync(0xffffffffu, tm, 4));
            tm = fmaxf(tm, __shfl_xor_sync(0xffffffffu, tm, 8));
            float mn = fmaxf(mrow[i], tm);
            float corr = __expf(mrow[i] - mn);
            mrow[i] = mn;
            float p0 = __expf(acc[i][0] - mn);
            float p1 = __expf(acc[i][1] - mn);
            float p2 = __expf(acc[i][2] - mn);
            float p3 = __expf(acc[i][3] - mn);
            float ts = (p0 + p1) + (p2 + p3);
            ts += __shfl_xor_sync(0xffffffffu, ts, 1);
            ts += __shfl_xor_sync(0xffffffffu, ts, 2);
            ts += __shfl_xor_sync(0xffffffffu, ts, 4);
            ts += __shfl_xor_sync(0xffffffffu, ts, 8);
            lrow[i] = lrow[i] * corr + ts;
#pragma unroll
            for (int jj = 0; jj < 8; jj++) o[i][jj] *= corr;
            float* prow = &Ps[(ty * 4 + i) * 65 + tx * 4];
            prow[0] = p0; prow[1] = p1; prow[2] = p2; prow[3] = p3;
        }
        __syncthreads();

        // O += P @ V  (4 rows x 8 d-cols per thread)
#pragma unroll 2
        for (int n = 0; n < FA_BN; n++) {
            float4 v0 = *(const float4*)&Vs[n * 128 + tx * 8];
            float4 v1 = *(const float4*)&Vs[n * 128 + tx * 8 + 4];
#pragma unroll
            for (int i = 0; i < 4; i++) {
                float p = Ps[(ty * 4 + i) * 65 + n];
                o[i][0] = fmaf(p, v0.x, o[i][0]);
                o[i][1] = fmaf(p, v0.y, o[i][1]);
                o[i][2] = fmaf(p, v0.z, o[i][2]);
                o[i][3] = fmaf(p, v0.w, o[i][3]);
                o[i][4] = fmaf(p, v1.x, o[i][4]);
                o[i][5] = fmaf(p, v1.y, o[i][5]);
                o[i][6] = fmaf(p, v1.z, o[i][6]);
                o[i][7] = fmaf(p, v1.w, o[i][7]);
            }
        }
    }

    // epilogue: O / l -> g_attn
#pragma unroll
    for (int i = 0; i < 4; i++) {
        float inv = 1.f / lrow[i];
        size_t orow = (size_t)(b * S_LEN + m0 + ty * 4 + i);
        float* op = &g_attn[orow * HID_C + h * HEAD_D + tx * 8];
        float4 r0, r1;
        r0.x = o[i][0] * inv; r0.y = o[i][1] * inv;
        r0.z = o[i][2] * inv; r0.w = o[i][3] * inv;
        r1.x = o[i][4] * inv; r1.y = o[i][5] * inv;
        r1.z = o[i][6] * inv; r1.w = o[i][7] * inv;
        *(float4*)op = r0;
        *(float4*)(op + 4) = r1;
    }
}

// ---------------------------------------------------------------------------
extern "C" void kernel_launch(void* const* d_in, const int* in_sizes, int n_in,
                              void* d_out, int out_size)
{
    (void)in_sizes; (void)n_in; (void)out_size;
    const float* hs  = (const float*)d_in[0];
    /* d_in[1] = attention_mask: exactly causal tril -> applied analytically */
    const float* Wq  = (const float*)d_in[2];
    const float* bq  = (const float*)d_in[3];
    const float* Wkv = (const float*)d_in[4];
    const float* bkv = (const float*)d_in[5];
    const float* Wp  = (const float*)d_in[6];
    const float* bp  = (const float*)d_in[7];
    float* out = (float*)d_out;

    float *pQ, *pKV, *pAttn;
    cudaGetSymbolAddress((void**)&pQ, g_Q);
    cudaGetSymbolAddress((void**)&pKV, g_KV);
    cudaGetSymbolAddress((void**)&pAttn, g_attn);

    dim3 blk(256);
    // Q = hs @ Wq + bq
    sgemm_bias_kernel<<<dim3(HID_C / 128, M_ROWS / 128), blk>>>(
        hs, Wq, bq, pQ, M_ROWS, HID_C, HID_C);
    // KV = hs @ Wkv + bkv
    sgemm_bias_kernel<<<dim3(KV_C / 128, M_ROWS / 128), blk>>>(
        hs, Wkv, bkv, pKV, M_ROWS, KV_C, HID_C);
    // attention
    cudaFuncSetAttribute(flash_attn_kernel,
                         cudaFuncAttributeMaxDynamicSharedMemorySize,
                         FA_SMEM_FLOATS * 4);
    flash_attn_kernel<<<dim3(S_LEN / FA_BM, N_HEADS, B_SZ), blk,
                        FA_SMEM_FLOATS * 4>>>();
    // out = attn @ Wp + bp
    sgemm_bias_kernel<<<dim3(HID_C / 128, M_ROWS / 128), blk>>>(
        pAttn, Wp, bp, out, M_ROWS, HID_C, HID_C);
}

// round 4
// speedup vs baseline: 1.4924x; 1.4924x over previous
#include <cuda_runtime.h>
#include <cuda_bf16.h>
#include <cstdint>

#define B_SZ 2
#define S_LEN 2048
#define HID_C 2048
#define N_HEADS 16
#define HEAD_D 128
#define M_ROWS (B_SZ * S_LEN)   /* 4096 */
#define KV_C 256

#define SOFTMAX_SCALE 0.08838834764831845f  /* 1/sqrt(128) */

// ---------------------------------------------------------------------------
// Device-global scratch (allocation-free rule)
// ---------------------------------------------------------------------------
__device__ float g_Q[(size_t)M_ROWS * HID_C];    // 33.5 MB
__device__ float g_KV[(size_t)M_ROWS * KV_C];    //  4.2 MB
__device__ __nv_bfloat16 gA_hi[(size_t)M_ROWS * HID_C];   // 16.8 MB
__device__ __nv_bfloat16 gA_lo[(size_t)M_ROWS * HID_C];
__device__ __nv_bfloat16 gWq_hi[(size_t)HID_C * HID_C];   // 8.4 MB
__device__ __nv_bfloat16 gWq_lo[(size_t)HID_C * HID_C];
__device__ __nv_bfloat16 gWkv_hi[(size_t)KV_C * HID_C];   // 1 MB
__device__ __nv_bfloat16 gWkv_lo[(size_t)KV_C * HID_C];
__device__ __nv_bfloat16 gWp_hi[(size_t)HID_C * HID_C];
__device__ __nv_bfloat16 gWp_lo[(size_t)HID_C * HID_C];

__device__ __forceinline__ uint32_t smem_to_u32(const void* p) {
    uint32_t a;
    asm("{ .reg .u64 t; cvta.to.shared.u64 t, %1; cvt.u32.u64 %0, t; }"
        : "=r"(a) : "l"(p));
    return a;
}

#define CP_ASYNC16(sm, g) \
    asm volatile("cp.async.cg.shared.global [%0], [%1], 16;" \
                 :: "r"(sm), "l"(g) : "memory")
#define CP_COMMIT() asm volatile("cp.async.commit_group;" ::: "memory")
#define CP_WAIT1()  asm volatile("cp.async.wait_group 1;" ::: "memory")

#define LDMATRIX_X4(r0, r1, r2, r3, addr) \
    asm volatile("ldmatrix.sync.aligned.m8n8.x4.shared.b16 {%0,%1,%2,%3}, [%4];" \
                 : "=r"(r0), "=r"(r1), "=r"(r2), "=r"(r3) : "r"(addr))

#define MMA_BF16(d, a, b) \
    asm volatile("mma.sync.aligned.m16n8k16.row.col.f32.bf16.bf16.f32 " \
                 "{%0,%1,%2,%3}, {%4,%5,%6,%7}, {%8,%9}, {%0,%1,%2,%3};" \
                 : "+f"((d)[0]), "+f"((d)[1]), "+f"((d)[2]), "+f"((d)[3]) \
                 : "r"((a)[0]), "r"((a)[1]), "r"((a)[2]), "r"((a)[3]), \
                   "r"((b)[0]), "r"((b)[1]))

// ---------------------------------------------------------------------------
// fp32 -> (hi, lo) bf16 split, elementwise (vectorized)
// ---------------------------------------------------------------------------
__global__ void split_f32_kernel(const float* __restrict__ src,
                                 __nv_bfloat16* __restrict__ hi,
                                 __nv_bfloat16* __restrict__ lo, int n4)
{
    int i = blockIdx.x * blockDim.x + threadIdx.x;
    if (i >= n4) return;
    float4 v = ((const float4*)src)[i];
    __nv_bfloat16 h0 = __float2bfloat16(v.x);
    __nv_bfloat16 h1 = __float2bfloat16(v.y);
    __nv_bfloat16 h2 = __float2bfloat16(v.z);
    __nv_bfloat16 h3 = __float2bfloat16(v.w);
    __nv_bfloat162 hh0; hh0.x = h0; hh0.y = h1;
    __nv_bfloat162 hh1; hh1.x = h2; hh1.y = h3;
    ((__nv_bfloat162*)hi)[2 * i] = hh0;
    ((__nv_bfloat162*)hi)[2 * i + 1] = hh1;
    __nv_bfloat162 ll0, ll1;
    ll0.x = __float2bfloat16(v.x - __bfloat162float(h0));
    ll0.y = __float2bfloat16(v.y - __bfloat162float(h1));
    ll1.x = __float2bfloat16(v.z - __bfloat162float(h2));
    ll1.y = __float2bfloat16(v.w - __bfloat162float(h3));
    ((__nv_bfloat162*)lo)[2 * i] = ll0;
    ((__nv_bfloat162*)lo)[2 * i + 1] = ll1;
}

// ---------------------------------------------------------------------------
// W[K][N] f32  ->  Wt_hi/lo[N][K] bf16 (transpose + split)
// ---------------------------------------------------------------------------
__global__ void tconv_kernel(const float* __restrict__ W,
                             __nv_bfloat16* __restrict__ Thi,
                             __nv_bfloat16* __restrict__ Tlo, int K, int N)
{
    __shared__ float tile[32][33];
    int n0 = blockIdx.x * 32, k0 = blockIdx.y * 32;
    int tx = threadIdx.x, ty = threadIdx.y;
#pragma unroll
    for (int j = 0; j < 32; j += 8)
        tile[ty + j][tx] = W[(size_t)(k0 + ty + j) * N + n0 + tx];
    __syncthreads();
#pragma unroll
    for (int j = 0; j < 32; j += 8) {
        float v = tile[tx][ty + j];
        __nv_bfloat16 h = __float2bfloat16(v);
        size_t o = (size_t)(n0 + ty + j) * K + k0 + tx;
        Thi[o] = h;
        Tlo[o] = __float2bfloat16(v - __bfloat162float(h));
    }
}

// ---------------------------------------------------------------------------
// mma.sync bf16 GEMM: C[M][N] = split3(A) @ split3(B)^T + bias
//   A: Ahi/Alo [M][2048] bf16 K-major; B: Bhi/Blo [N][2048] bf16 K-major.
//   3-term emulation via extended K (192 chunks of 32): phases hi.hi/lo.hi/hi.lo
// CTA 128x128, 8 warps (2x4), warp tile 64x32, 3-stage cp.async pipeline.
// smem rows pitched to 80B: 16B-group index (5r mod 8) => conflict-free ldmatrix.
// ---------------------------------------------------------------------------
#define BM 128
#define BN 128
#define BKH 32                  /* halves per chunk */
#define APITCH_B 80             /* bytes per smem row */
#define STG_A (BM * APITCH_B)   /* 10240 B */
#define STG_B (BN * APITCH_B)
#define STG_BYTES (STG_A + STG_B)  /* 20480 */
#define NSTAGE 3
#define GEMM_SMEM (NSTAGE * STG_BYTES)  /* 61440 */
#define NCHUNK 192              /* 3 * 2048 / 32 */

__global__ __launch_bounds__(256, 2)
void mma_gemm_kernel(const __nv_bfloat16* __restrict__ Ahi,
                     const __nv_bfloat16* __restrict__ Alo,
                     const __nv_bfloat16* __restrict__ Bhi,
                     const __nv_bfloat16* __restrict__ Blo,
                     const float* __restrict__ bias,
                     float* __restrict__ C, int N)
{
    extern __shared__ char smem[];
    const uint32_t smem_base = smem_to_u32(smem);
    const int tid = threadIdx.x;
    const int wid = tid >> 5;
    const int lid = tid & 31;
    const int bm = blockIdx.y * BM;
    const int bn = blockIdx.x * BN;

    // ---- cp.async issue for one chunk into one stage ----
    auto issue = [&](int c, int stage) {
        const __nv_bfloat16* Asrc = ((c >> 6) == 1) ? Alo : Ahi;
        const __nv_bfloat16* Bsrc = ((c >> 6) == 2) ? Blo : Bhi;
        const size_t k0 = (size_t)(c & 63) * BKH;
        const uint32_t sA = smem_base + stage * STG_BYTES;
        const uint32_t sB = sA + STG_A;
#pragma unroll
        for (int j = 0; j < 2; j++) {
            int seg = tid + j * 256;
            int r = seg >> 2, s = seg & 3;
            CP_ASYNC16(sA + r * APITCH_B + s * 16,
                       (const char*)(Asrc + (size_t)(bm + r) * HID_C + k0 + s * 8));
        }
#pragma unroll
        for (int j = 0; j < 2; j++) {
            int seg = tid + j * 256;
            int r = seg >> 2, s = seg & 3;
            CP_ASYNC16(sB + r * APITCH_B + s * 16,
                       (const char*)(Bsrc + (size_t)(bn + r) * HID_C + k0 + s * 8));
        }
    };

    float acc[4][4][4];
#pragma unroll
    for (int i = 0; i < 4; i++)
#pragma unroll
        for (int j = 0; j < 4; j++)
#pragma unroll
            for (int q = 0; q < 4; q++) acc[i][j][q] = 0.f;

    issue(0, 0); CP_COMMIT();
    issue(1, 1); CP_COMMIT();

    const int wm = (wid >> 2) * 64;
    const int wn = (wid & 3) * 32;
    const int mat = lid >> 3;
    const int wi = lid & 7;

    for (int t = 0; t < NCHUNK; t++) {
        CP_WAIT1();
        __syncthreads();
        if (t + 2 < NCHUNK) issue(t + 2, (t + 2) % NSTAGE);
        CP_COMMIT();

        const uint32_t aBase = smem_base + (t % NSTAGE) * STG_BYTES;
        const uint32_t bBase = aBase + STG_A;
#pragma unroll
        for (int ks = 0; ks < 2; ks++) {
            const int k0 = ks * 16;
            uint32_t afr[4][4];
            uint32_t bfr[4][2];
#pragma unroll
            for (int i = 0; i < 4; i++) {
                int row = wm + i * 16 + (mat & 1) * 8 + wi;
                int col = k0 + (mat >> 1) * 8;
                LDMATRIX_X4(afr[i][0], afr[i][1], afr[i][2], afr[i][3],
                            aBase + row * APITCH_B + col * 2);
            }
#pragma unroll
            for (int jj = 0; jj < 2; jj++) {
                int n = wn + jj * 16 + (mat >> 1) * 8 + wi;
                int k = k0 + (mat & 1) * 8;
                LDMATRIX_X4(bfr[2 * jj][0], bfr[2 * jj][1],
                            bfr[2 * jj + 1][0], bfr[2 * jj + 1][1],
                            bBase + n * APITCH_B + k * 2);
            }
#pragma unroll
            for (int i = 0; i < 4; i++)
#pragma unroll
                for (int j = 0; j < 4; j++)
                    MMA_BF16(acc[i][j], afr[i], bfr[j]);
        }
    }

    // epilogue: c0,c1 = (row g, cols 2t,2t+1); c2,c3 = (row g+8)
    const int g = lid >> 2;
    const int tq = lid & 3;
#pragma unroll
    for (int i = 0; i < 4; i++) {
#pragma unroll
        for (int j = 0; j < 4; j++) {
            int row0 = bm + wm + i * 16 + g;
            int col = bn + wn + j * 8 + tq * 2;
            float b0 = bias[col], b1 = bias[col + 1];
            float2 r0 = make_float2(acc[i][j][0] + b0, acc[i][j][1] + b1);
            float2 r1 = make_float2(acc[i][j][2] + b0, acc[i][j][3] + b1);
            *(float2*)(C + (size_t)row0 * N + col) = r0;
            *(float2*)(C + (size_t)(row0 + 8) * N + col) = r1;
        }
    }
}

// ---------------------------------------------------------------------------
// Flash attention (causal, fp32) — epilogue writes bf16 hi/lo split directly
// ---------------------------------------------------------------------------
#define FA_BM 64
#define FA_BN 64
#define QS_OFF 0
#define KS_OFF (128 * 64)
#define VS_OFF (2 * 128 * 64)
#define PS_OFF (2 * 128 * 64 + 64 * 128)
#define FA_SMEM_FLOATS (3 * 128 * 64 + 64 * 65)

__global__ __launch_bounds__(256, 2)
void flash_attn_kernel()
{
    extern __shared__ float smf[];
    float* Qs = smf + QS_OFF;
    float* Ks = smf + KS_OFF;
    float* Vs = smf + VS_OFF;
    float* Ps = smf + PS_OFF;

    const int tid = threadIdx.x;
    const int tx = tid & 15;
    const int ty = tid >> 4;
    const int qt = (int)gridDim.x - 1 - (int)blockIdx.x;
    const int h = blockIdx.y;
    const int b = blockIdx.z;
    const int m0 = qt * FA_BM;

    const size_t qrow0 = (size_t)(b * S_LEN + m0);

#pragma unroll
    for (int it = 0; it < 8; it++) {
        int i = tid + it * 256;
        int r = i >> 5;
        int c4 = (i & 31) * 4;
        float4 q4 = *(const float4*)&g_Q[(qrow0 + r) * HID_C + h * HEAD_D + c4];
        int swo = (((r >> 2) ^ ((c4 >> 2) & 15)) << 2) + (r & 3);
        Qs[(c4 + 0) * 64 + swo] = q4.x;
        Qs[(c4 + 1) * 64 + swo] = q4.y;
        Qs[(c4 + 2) * 64 + swo] = q4.z;
        Qs[(c4 + 3) * 64 + swo] = q4.w;
    }

    float o[4][8];
#pragma unroll
    for (int i = 0; i < 4; i++)
#pragma unroll
        for (int j = 0; j < 8; j++) o[i][j] = 0.f;
    float mrow[4] = {-1e30f, -1e30f, -1e30f, -1e30f};
    float lrow[4] = {0.f, 0.f, 0.f, 0.f};

    const size_t kvrow0 = (size_t)b * S_LEN;

    for (int t = 0; t <= qt; t++) {
        const int n0 = t * FA_BN;
        __syncthreads();
#pragma unroll
        for (int it = 0; it < 8; it++) {
            int i = tid + it * 256;
            int r = i >> 5;
            int c4 = (i & 31) * 4;
            const float* kvp = &g_KV[(kvrow0 + n0 + r) * KV_C];
            float4 k4 = *(const float4*)(kvp + c4);
            int swo = (((r >> 2) ^ ((c4 >> 2) & 15)) << 2) + (r & 3);
            Ks[(c4 + 0) * 64 + swo] = k4.x;
            Ks[(c4 + 1) * 64 + swo] = k4.y;
            Ks[(c4 + 2) * 64 + swo] = k4.z;
            Ks[(c4 + 3) * 64 + swo] = k4.w;
            float4 v4 = *(const float4*)(kvp + HEAD_D + c4);
            *(float4*)&Vs[r * 128 + c4] = v4;
        }
        __syncthreads();

        float acc[4][4];
#pragma unroll
        for (int i = 0; i < 4; i++)
#pragma unroll
            for (int j = 0; j < 4; j++) acc[i][j] = 0.f;

#pragma unroll 2
        for (int d4 = 0; d4 < 32; d4++) {
            const int sw = d4 & 15;
            const float* qrow = &Qs[d4 * 4 * 64];
            const float* krow = &Ks[d4 * 4 * 64];
            const int aoff = (ty ^ sw) << 2;
            const int boff = (tx ^ sw) << 2;
#pragma unroll
            for (int dd = 0; dd < 4; dd++) {
                float4 a = *(const float4*)&qrow[dd * 64 + aoff];
                float4 bk = *(const float4*)&krow[dd * 64 + boff];
                acc[0][0] = fmaf(a.x, bk.x, acc[0][0]);
                acc[0][1] = fmaf(a.x, bk.y, acc[0][1]);
                acc[0][2] = fmaf(a.x, bk.z, acc[0][2]);
                acc[0][3] = fmaf(a.x, bk.w, acc[0][3]);
                acc[1][0] = fmaf(a.y, bk.x, acc[1][0]);
                acc[1][1] = fmaf(a.y, bk.y, acc[1][1]);
                acc[1][2] = fmaf(a.y, bk.z, acc[1][2]);
                acc[1][3] = fmaf(a.y, bk.w, acc[1][3]);
                acc[2][0] = fmaf(a.z, bk.x, acc[2][0]);
                acc[2][1] = fmaf(a.z, bk.y, acc[2][1]);
                acc[2][2] = fmaf(a.z, bk.z, acc[2][2]);
                acc[2][3] = fmaf(a.z, bk.w, acc[2][3]);
                acc[3][0] = fmaf(a.w, bk.x, acc[3][0]);
                acc[3][1] = fmaf(a.w, bk.y, acc[3][1]);
                acc[3][2] = fmaf(a.w, bk.z, acc[3][2]);
                acc[3][3] = fmaf(a.w, bk.w, acc[3][3]);
            }
        }

        const bool diag = (t == qt);
#pragma unroll
        for (int i = 0; i < 4; i++) {
#pragma unroll
            for (int j = 0; j < 4; j++) {
                float s = acc[i][j] * SOFTMAX_SCALE;
                if (diag && (tx * 4 + j > ty * 4 + i)) s = -1e30f;
                acc[i][j] = s;
            }
            float tm = fmaxf(fmaxf(acc[i][0], acc[i][1]), fmaxf(acc[i][2], acc[i][3]));
            tm = fmaxf(tm, __shfl_xor_sync(0xffffffffu, tm, 1));
            tm = fmaxf(tm, __shfl_xor_sync(0xffffffffu, tm, 2));
            tm = fmaxf(tm, __shfl_xor_sync(0xffffffffu, tm, 4));
            tm = fmaxf(tm, __shfl_xor_sync(0xffffffffu, tm, 8));
            float mn = fmaxf(mrow[i], tm);
            float corr = __expf(mrow[i] - mn);
            mrow[i] = mn;
            float p0 = __expf(acc[i][0] - mn);
            float p1 = __expf(acc[i][1] - mn);
            float p2 = __expf(acc[i][2] - mn);
            float p3 = __expf(acc[i][3] - mn);
            float ts = (p0 + p1) + (p2 + p3);
            ts += __shfl_xor_sync(0xffffffffu, ts, 1);
            ts += __shfl_xor_sync(0xffffffffu, ts, 2);
            ts += __shfl_xor_sync(0xffffffffu, ts, 4);
            ts += __shfl_xor_sync(0xffffffffu, ts, 8);
            lrow[i] = lrow[i] * corr + ts;
#pragma unroll
            for (int jj = 0; jj < 8; jj++) o[i][jj] *= corr;
            float* prow = &Ps[(ty * 4 + i) * 65 + tx * 4];
            prow[0] = p0; prow[1] = p1; prow[2] = p2; prow[3] = p3;
        }
        __syncthreads();

#pragma unroll 2
        for (int n = 0; n < FA_BN; n++) {
            float4 v0 = *(const float4*)&Vs[n * 128 + tx * 8];
            float4 v1 = *(const float4*)&Vs[n * 128 + tx * 8 + 4];
#pragma unroll
            for (int i = 0; i < 4; i++) {
                float p = Ps[(ty * 4 + i) * 65 + n];
                o[i][0] = fmaf(p, v0.x, o[i][0]);
                o[i][1] = fmaf(p, v0.y, o[i][1]);
                o[i][2] = fmaf(p, v0.z, o[i][2]);
                o[i][3] = fmaf(p, v0.w, o[i][3]);
                o[i][4] = fmaf(p, v1.x, o[i][4]);
                o[i][5] = fmaf(p, v1.y, o[i][5]);
                o[i][6] = fmaf(p, v1.z, o[i][6]);
                o[i][7] = fmaf(p, v1.w, o[i][7]);
            }
        }
    }

    // epilogue: O/l -> bf16 hi/lo split written straight to gA_hi/gA_lo
#pragma unroll
    for (int i = 0; i < 4; i++) {
        float inv = 1.f / lrow[i];
        size_t orow = (size_t)(b * S_LEN + m0 + ty * 4 + i);
        size_t off = orow * HID_C + h * HEAD_D + tx * 8;
        __nv_bfloat16 hb[8], lb[8];
#pragma unroll
        for (int jj = 0; jj < 8; jj++) {
            float v = o[i][jj] * inv;
            __nv_bfloat16 bh = __float2bfloat16(v);
            hb[jj] = bh;
            lb[jj] = __float2bfloat16(v - __bfloat162float(bh));
        }
        *(uint4*)&gA_hi[off] = *(uint4*)hb;
        *(uint4*)&gA_lo[off] = *(uint4*)lb;
    }
}

// ---------------------------------------------------------------------------
extern "C" void kernel_launch(void* const* d_in, const int* in_sizes, int n_in,
                              void* d_out, int out_size)
{
    (void)in_sizes; (void)n_in; (void)out_size;
    const float* hs  = (const float*)d_in[0];
    /* d_in[1] = attention_mask (exact causal tril) applied analytically */
    const float* Wq  = (const float*)d_in[2];
    const float* bq  = (const float*)d_in[3];
    const float* Wkv = (const float*)d_in[4];
    const float* bkv = (const float*)d_in[5];
    const float* Wp  = (const float*)d_in[6];
    const float* bp  = (const float*)d_in[7];
    float* out = (float*)d_out;

    float *pQ, *pKV;
    cudaGetSymbolAddress((void**)&pQ, g_Q);
    cudaGetSymbolAddress((void**)&pKV, g_KV);
    __nv_bfloat16 *pAhi, *pAlo, *pWqh, *pWql, *pWkh, *pWkl, *pWph, *pWpl;
    cudaGetSymbolAddress((void**)&pAhi, gA_hi);
    cudaGetSymbolAddress((void**)&pAlo, gA_lo);
    cudaGetSymbolAddress((void**)&pWqh, gWq_hi);
    cudaGetSymbolAddress((void**)&pWql, gWq_lo);
    cudaGetSymbolAddress((void**)&pWkh, gWkv_hi);
    cudaGetSymbolAddress((void**)&pWkl, gWkv_lo);
    cudaGetSymbolAddress((void**)&pWph, gWp_hi);
    cudaGetSymbolAddress((void**)&pWpl, gWp_lo);

    cudaFuncSetAttribute(mma_gemm_kernel,
                         cudaFuncAttributeMaxDynamicSharedMemorySize, GEMM_SMEM);
    cudaFuncSetAttribute(flash_attn_kernel,
                         cudaFuncAttributeMaxDynamicSharedMemorySize,
                         FA_SMEM_FLOATS * 4);

    // 1. split hidden states into bf16 hi/lo
    {
        int n4 = M_ROWS * HID_C / 4;
        split_f32_kernel<<<(n4 + 255) / 256, 256>>>(hs, pAhi, pAlo, n4);
    }
    // 2. transpose+split weights
    tconv_kernel<<<dim3(HID_C / 32, HID_C / 32), dim3(32, 8)>>>(Wq, pWqh, pWql, HID_C, HID_C);
    tconv_kernel<<<dim3(KV_C / 32, HID_C / 32), dim3(32, 8)>>>(Wkv, pWkh, pWkl, HID_C, KV_C);
    tconv_kernel<<<dim3(HID_C / 32, HID_C / 32), dim3(32, 8)>>>(Wp, pWph, pWpl, HID_C, HID_C);

    // 3. Q = hs @ Wq + bq   (tensor-core mma.sync)
    mma_gemm_kernel<<<dim3(HID_C / BN, M_ROWS / BM), 256, GEMM_SMEM>>>(
        pAhi, pAlo, pWqh, pWql, bq, pQ, HID_C);
    // 4. KV = hs @ Wkv + bkv
    mma_gemm_kernel<<<dim3(KV_C / BN, M_ROWS / BM), 256, GEMM_SMEM>>>(
        pAhi, pAlo, pWkh, pWkl, bkv, pKV, KV_C);
    // 5. attention (writes bf16 hi/lo of attn into gA_hi/gA_lo)
    flash_attn_kernel<<<dim3(S_LEN / FA_BM, N_HEADS, B_SZ), 256,
                        FA_SMEM_FLOATS * 4>>>();
    // 6. out = attn @ Wp + bp
    mma_gemm_kernel<<<dim3(HID_C / BN, M_ROWS / BM), 256, GEMM_SMEM>>>(
        pAhi, pAlo, pWph, pWpl, bp, out, HID_C);
}

// round 5
// speedup vs baseline: 2.6812x; 1.7965x over previous
#include <cuda_runtime.h>
#include <cuda_bf16.h>
#include <cstdint>

#define B_SZ 2
#define S_LEN 2048
#define HID_C 2048
#define N_HEADS 16
#define HEAD_D 128
#define M_ROWS (B_SZ * S_LEN)   /* 4096 */
#define KV_C 256

#define SOFTMAX_SCALE 0.08838834764831845f  /* 1/sqrt(128) */

// ---------------------------------------------------------------------------
// Device-global scratch (allocation-free rule)
// ---------------------------------------------------------------------------
__device__ __nv_bfloat16 gA_hi[(size_t)M_ROWS * HID_C];   // hs / attn hi
__device__ __nv_bfloat16 gA_lo[(size_t)M_ROWS * HID_C];
__device__ __nv_bfloat16 gQhi[(size_t)M_ROWS * HID_C];
__device__ __nv_bfloat16 gQlo[(size_t)M_ROWS * HID_C];
__device__ __nv_bfloat16 gKhi[(size_t)M_ROWS * HEAD_D];
__device__ __nv_bfloat16 gKlo[(size_t)M_ROWS * HEAD_D];
__device__ __nv_bfloat16 gVthi[(size_t)HEAD_D * M_ROWS];  // V transposed [d][bS]
__device__ __nv_bfloat16 gVtlo[(size_t)HEAD_D * M_ROWS];
__device__ __nv_bfloat16 gWq_hi[(size_t)HID_C * HID_C];
__device__ __nv_bfloat16 gWq_lo[(size_t)HID_C * HID_C];
__device__ __nv_bfloat16 gWkv_hi[(size_t)KV_C * HID_C];
__device__ __nv_bfloat16 gWkv_lo[(size_t)KV_C * HID_C];
__device__ __nv_bfloat16 gWp_hi[(size_t)HID_C * HID_C];
__device__ __nv_bfloat16 gWp_lo[(size_t)HID_C * HID_C];

__device__ __forceinline__ uint32_t smem_to_u32(const void* p) {
    uint32_t a;
    asm("{ .reg .u64 t; cvta.to.shared.u64 t, %1; cvt.u32.u64 %0, t; }"
        : "=r"(a) : "l"(p));
    return a;
}

#define CP_ASYNC16(sm, g) \
    asm volatile("cp.async.cg.shared.global [%0], [%1], 16;" \
                 :: "r"(sm), "l"(g) : "memory")
#define CP_COMMIT() asm volatile("cp.async.commit_group;" ::: "memory")
#define CP_WAIT1()  asm volatile("cp.async.wait_group 1;" ::: "memory")
#define CP_WAIT0()  asm volatile("cp.async.wait_group 0;" ::: "memory")

#define LDMATRIX_X4(r0, r1, r2, r3, addr) \
    asm volatile("ldmatrix.sync.aligned.m8n8.x4.shared.b16 {%0,%1,%2,%3}, [%4];" \
                 : "=r"(r0), "=r"(r1), "=r"(r2), "=r"(r3) : "r"(addr))

#define MMA_BF16(d, a, b) \
    asm volatile("mma.sync.aligned.m16n8k16.row.col.f32.bf16.bf16.f32 " \
                 "{%0,%1,%2,%3}, {%4,%5,%6,%7}, {%8,%9}, {%0,%1,%2,%3};" \
                 : "+f"((d)[0]), "+f"((d)[1]), "+f"((d)[2]), "+f"((d)[3]) \
                 : "r"((a)[0]), "r"((a)[1]), "r"((a)[2]), "r"((a)[3]), \
                   "r"((b)[0]), "r"((b)[1]))

__device__ __forceinline__ uint32_t pack_bf16(float x, float y) {
    __nv_bfloat162 t = __float22bfloat162_rn(make_float2(x, y));
    return *reinterpret_cast<uint32_t*>(&t);
}
__device__ __forceinline__ void split2(float v0, float v1,
                                       uint32_t& hi, uint32_t& lo) {
    __nv_bfloat16 h0 = __float2bfloat16(v0);
    __nv_bfloat16 h1 = __float2bfloat16(v1);
    __nv_bfloat162 hh; hh.x = h0; hh.y = h1;
    hi = *reinterpret_cast<uint32_t*>(&hh);
    lo = pack_bf16(v0 - __bfloat162float(h0), v1 - __bfloat162float(h1));
}

// ---------------------------------------------------------------------------
// fp32 -> (hi, lo) bf16 split, elementwise
// ---------------------------------------------------------------------------
__global__ void split_f32_kernel(const float* __restrict__ src,
                                 __nv_bfloat16* __restrict__ hi,
                                 __nv_bfloat16* __restrict__ lo, int n4)
{
    int i = blockIdx.x * blockDim.x + threadIdx.x;
    if (i >= n4) return;
    float4 v = ((const float4*)src)[i];
    uint32_t h0, l0, h1, l1;
    split2(v.x, v.y, h0, l0);
    split2(v.z, v.w, h1, l1);
    ((uint32_t*)hi)[2 * i] = h0;
    ((uint32_t*)hi)[2 * i + 1] = h1;
    ((uint32_t*)lo)[2 * i] = l0;
    ((uint32_t*)lo)[2 * i + 1] = l1;
}

// ---------------------------------------------------------------------------
// W[K][N] f32 -> Wt_hi/lo[N][K] bf16 (transpose + split)
// ---------------------------------------------------------------------------
__global__ void tconv_kernel(const float* __restrict__ W,
                             __nv_bfloat16* __restrict__ Thi,
                             __nv_bfloat16* __restrict__ Tlo, int K, int N)
{
    __shared__ float tile[32][33];
    int n0 = blockIdx.x * 32, k0 = blockIdx.y * 32;
    int tx = threadIdx.x, ty = threadIdx.y;
#pragma unroll
    for (int j = 0; j < 32; j += 8)
        tile[ty + j][tx] = W[(size_t)(k0 + ty + j) * N + n0 + tx];
    __syncthreads();
#pragma unroll
    for (int j = 0; j < 32; j += 8) {
        float v = tile[tx][ty + j];
        __nv_bfloat16 h = __float2bfloat16(v);
        size_t o = (size_t)(n0 + ty + j) * K + k0 + tx;
        Thi[o] = h;
        Tlo[o] = __float2bfloat16(v - __bfloat162float(h));
    }
}

// ---------------------------------------------------------------------------
// mma.sync bf16 GEMM: C = split3(A) @ split3(B)^T + bias
// mode 0: fp32 C.  mode 1: bf16 hi/lo split -> gQhi/gQlo.
// mode 2: KV: bn==0 -> K hi/lo [bS][128]; bn==128 -> V^T hi/lo [d][bS].
// ---------------------------------------------------------------------------
#define BM 128
#define BN 128
#define BKH 32
#define APITCH_B 80
#define STG_A (BM * APITCH_B)
#define STG_B (BN * APITCH_B)
#define STG_BYTES (STG_A + STG_B)
#define NSTAGE 3
#define GEMM_SMEM (NSTAGE * STG_BYTES)
#define NCHUNK 192

__global__ __launch_bounds__(256, 2)
void mma_gemm_kernel(const __nv_bfloat16* __restrict__ Ahi,
                     const __nv_bfloat16* __restrict__ Alo,
                     const __nv_bfloat16* __restrict__ Bhi,
                     const __nv_bfloat16* __restrict__ Blo,
                     const float* __restrict__ bias,
                     float* __restrict__ C, int N, int mode)
{
    extern __shared__ char smem[];
    const uint32_t smem_base = smem_to_u32(smem);
    const int tid = threadIdx.x;
    const int wid = tid >> 5;
    const int lid = tid & 31;
    const int bm = blockIdx.y * BM;
    const int bn = blockIdx.x * BN;

    auto issue = [&](int c, int stage) {
        const __nv_bfloat16* Asrc = ((c >> 6) == 1) ? Alo : Ahi;
        const __nv_bfloat16* Bsrc = ((c >> 6) == 2) ? Blo : Bhi;
        const size_t k0 = (size_t)(c & 63) * BKH;
        const uint32_t sA = smem_base + stage * STG_BYTES;
        const uint32_t sB = sA + STG_A;
#pragma unroll
        for (int j = 0; j < 2; j++) {
            int seg = tid + j * 256;
            int r = seg >> 2, s = seg & 3;
            CP_ASYNC16(sA + r * APITCH_B + s * 16,
                       (const char*)(Asrc + (size_t)(bm + r) * HID_C + k0 + s * 8));
        }
#pragma unroll
        for (int j = 0; j < 2; j++) {
            int seg = tid + j * 256;
            int r = seg >> 2, s = seg & 3;
            CP_ASYNC16(sB + r * APITCH_B + s * 16,
                       (const char*)(Bsrc + (size_t)(bn + r) * HID_C + k0 + s * 8));
        }
    };

    float acc[4][4][4];
#pragma unroll
    for (int i = 0; i < 4; i++)
#pragma unroll
        for (int j = 0; j < 4; j++)
#pragma unroll
            for (int q = 0; q < 4; q++) acc[i][j][q] = 0.f;

    issue(0, 0); CP_COMMIT();
    issue(1, 1); CP_COMMIT();

    const int wm = (wid >> 2) * 64;
    const int wn = (wid & 3) * 32;
    const int mat = lid >> 3;
    const int wi = lid & 7;

    for (int t = 0; t < NCHUNK; t++) {
        CP_WAIT1();
        __syncthreads();
        if (t + 2 < NCHUNK) issue(t + 2, (t + 2) % NSTAGE);
        CP_COMMIT();

        const uint32_t aBase = smem_base + (t % NSTAGE) * STG_BYTES;
        const uint32_t bBase = aBase + STG_A;
#pragma unroll
        for (int ks = 0; ks < 2; ks++) {
            const int k0 = ks * 16;
            uint32_t afr[4][4];
            uint32_t bfr[4][2];
#pragma unroll
            for (int i = 0; i < 4; i++) {
                int row = wm + i * 16 + (mat & 1) * 8 + wi;
                int col = k0 + (mat >> 1) * 8;
                LDMATRIX_X4(afr[i][0], afr[i][1], afr[i][2], afr[i][3],
                            aBase + row * APITCH_B + col * 2);
            }
#pragma unroll
            for (int jj = 0; jj < 2; jj++) {
                int n = wn + jj * 16 + (mat >> 1) * 8 + wi;
                int k = k0 + (mat & 1) * 8;
                LDMATRIX_X4(bfr[2 * jj][0], bfr[2 * jj][1],
                            bfr[2 * jj + 1][0], bfr[2 * jj + 1][1],
                            bBase + n * APITCH_B + k * 2);
            }
#pragma unroll
            for (int i = 0; i < 4; i++)
#pragma unroll
                for (int j = 0; j < 4; j++)
                    MMA_BF16(acc[i][j], afr[i], bfr[j]);
        }
    }

    const int g = lid >> 2;
    const int tq = lid & 3;
#pragma unroll
    for (int i = 0; i < 4; i++) {
#pragma unroll
        for (int j = 0; j < 4; j++) {
            int row0 = bm + wm + i * 16 + g;
            int col = bn + wn + j * 8 + tq * 2;
            float b0 = bias[col], b1 = bias[col + 1];
            float v00 = acc[i][j][0] + b0, v01 = acc[i][j][1] + b1;
            float v10 = acc[i][j][2] + b0, v11 = acc[i][j][3] + b1;
            if (mode == 0) {
                *(float2*)(C + (size_t)row0 * N + col) = make_float2(v00, v01);
                *(float2*)(C + (size_t)(row0 + 8) * N + col) = make_float2(v10, v11);
            } else if (mode == 1) {
                uint32_t h, l;
                split2(v00, v01, h, l);
                *(uint32_t*)&gQhi[(size_t)row0 * HID_C + col] = h;
                *(uint32_t*)&gQlo[(size_t)row0 * HID_C + col] = l;
                split2(v10, v11, h, l);
                *(uint32_t*)&gQhi[(size_t)(row0 + 8) * HID_C + col] = h;
                *(uint32_t*)&gQlo[(size_t)(row0 + 8) * HID_C + col] = l;
            } else {
                if (bn == 0) {  // K part
                    uint32_t h, l;
                    split2(v00, v01, h, l);
                    *(uint32_t*)&gKhi[(size_t)row0 * HEAD_D + col] = h;
                    *(uint32_t*)&gKlo[(size_t)row0 * HEAD_D + col] = l;
                    split2(v10, v11, h, l);
                    *(uint32_t*)&gKhi[(size_t)(row0 + 8) * HEAD_D + col] = h;
                    *(uint32_t*)&gKlo[(size_t)(row0 + 8) * HEAD_D + col] = l;
                } else {        // V part -> transposed
                    int d0 = col - 128;
                    float vs[2][2] = {{v00, v01}, {v10, v11}};
#pragma unroll
                    for (int rr = 0; rr < 2; rr++)
#pragma unroll
                        for (int cc = 0; cc < 2; cc++) {
                            float v = vs[rr][cc];
                            __nv_bfloat16 h = __float2bfloat16(v);
                            size_t o = (size_t)(d0 + cc) * M_ROWS + row0 + rr * 8;
                            gVthi[o] = h;
                            gVtlo[o] = __float2bfloat16(v - __bfloat162float(h));
                        }
                }
            }
        }
    }
}

// ---------------------------------------------------------------------------
// Flash attention, tensor-core (mma.sync bf16, 3-term splits), causal.
// CTA: 128 q-rows x (one head, one batch); 8 warps, warp = m16. BN=64 kv.
// Smem: Q hi/lo [128][128] + 2 stages of {K hi/lo [64][128], Vt hi/lo [128][64]}
// ---------------------------------------------------------------------------
#define FM 128
#define FN 64
#define SMQ_HI 0
#define SMQ_LO 32768
#define SM_STG 65536
#define STGSZ 65536
#define SK_HI 0
#define SK_LO 16384
#define SV_HI 32768
#define SV_LO 49152
#define FA_SMEM (65536 + 2 * 65536)   /* 196608 */

__global__ __launch_bounds__(256, 1)
void flash_mma_kernel()
{
    extern __shared__ char sm[];
    const uint32_t sb = smem_to_u32(sm);
    const int tid = threadIdx.x;
    const int wid = tid >> 5;
    const int lid = tid & 31;
    const int qt = (int)gridDim.x - 1 - (int)blockIdx.x;
    const int h = blockIdx.y;
    const int b = blockIdx.z;
    const int m0 = qt * FM;
    const int wm = wid * 16;
    const size_t bS = (size_t)b * S_LEN;
    const int g = lid >> 2, tq = lid & 3;
    const int ntiles = 2 * qt + 2;

    auto issueQ = [&]() {
#pragma unroll
        for (int j = 0; j < 16; j++) {
            int idx = tid + j * 256;
            int arr = idx >> 11;
            int rem = idx & 2047;
            int r = rem >> 4, c16 = rem & 15;
            const __nv_bfloat16* src =
                (arr ? gQlo : gQhi) + (bS + m0 + r) * HID_C + h * HEAD_D + c16 * 8;
            CP_ASYNC16(sb + (arr ? SMQ_LO : SMQ_HI) + r * 256 + ((c16 ^ (r & 7)) << 4),
                       (const char*)src);
        }
    };
    auto issueKV = [&](int t, int s) {
        const uint32_t st = sb + SM_STG + s * STGSZ;
        const int n0 = t * FN;
#pragma unroll
        for (int j = 0; j < 8; j++) {
            int idx = tid + j * 256;
            int arr = idx >> 10;
            int rem = idx & 1023;
            int r = rem >> 4, c16 = rem & 15;
            const __nv_bfloat16* src =
                (arr ? gKlo : gKhi) + (bS + n0 + r) * HEAD_D + c16 * 8;
            CP_ASYNC16(st + (arr ? SK_LO : SK_HI) + r * 256 + ((c16 ^ (r & 7)) << 4),
                       (const char*)src);
        }
#pragma unroll
        for (int j = 0; j < 8; j++) {
            int idx = tid + j * 256;
            int arr = idx >> 10;
            int rem = idx & 1023;
            int r = rem >> 3, c16 = rem & 7;
            const __nv_bfloat16* src =
                (arr ? gVtlo : gVthi) + (size_t)r * M_ROWS + bS + n0 + c16 * 8;
            CP_ASYNC16(st + (arr ? SV_LO : SV_HI) + r * 128 + ((c16 ^ (r & 7)) << 4),
                       (const char*)src);
        }
    };

    issueQ();
    issueKV(0, 0);
    CP_COMMIT();
    issueKV(1, 1);
    CP_COMMIT();
    CP_WAIT1();
    __syncthreads();

    float oacc[16][4];
#pragma unroll
    for (int i = 0; i < 16; i++)
#pragma unroll
        for (int q = 0; q < 4; q++) oacc[i][q] = 0.f;
    float mst[2] = {-1e30f, -1e30f};
    float lst[2] = {0.f, 0.f};

    const int mat = lid >> 3;
    const int wi = lid & 7;

    for (int t = 0; t < ntiles; t++) {
        const uint32_t st = sb + SM_STG + (t & 1) * STGSZ;

        // ---- S = Q K^T (3 passes) ----
        float sacc[8][4];
#pragma unroll
        for (int i = 0; i < 8; i++)
#pragma unroll
            for (int q = 0; q < 4; q++) sacc[i][q] = 0.f;

#pragma unroll
        for (int pass = 0; pass < 3; pass++) {
            const uint32_t qb = sb + (pass == 1 ? SMQ_LO : SMQ_HI);
            const uint32_t kb = st + (pass == 2 ? SK_LO : SK_HI);
#pragma unroll
            for (int kk = 0; kk < 8; kk++) {
                uint32_t a[4];
                {
                    int r = wm + (lid & 15);
                    int c16 = 2 * kk + (lid >> 4);
                    LDMATRIX_X4(a[0], a[1], a[2], a[3],
                                qb + r * 256 + ((c16 ^ (r & 7)) << 4));
                }
                uint32_t bf[8][2];
#pragma unroll
                for (int jj = 0; jj < 4; jj++) {
                    int r = jj * 16 + (mat >> 1) * 8 + wi;
                    int c16 = 2 * kk + (mat & 1);
                    LDMATRIX_X4(bf[2 * jj][0], bf[2 * jj][1],
                                bf[2 * jj + 1][0], bf[2 * jj + 1][1],
                                kb + r * 256 + ((c16 ^ (r & 7)) << 4));
                }
#pragma unroll
                for (int nb = 0; nb < 8; nb++)
                    MMA_BF16(sacc[nb], a, bf[nb]);
            }
        }

        // ---- softmax (online) ----
        const bool dg = (t >= 2 * qt);
#pragma unroll
        for (int hf = 0; hf < 2; hf++) {
            const int row = m0 + wm + g + hf * 8;
            float tm = -1e30f;
#pragma unroll
            for (int nb = 0; nb < 8; nb++) {
#pragma unroll
                for (int e = 0; e < 2; e++) {
                    float s = sacc[nb][2 * hf + e] * SOFTMAX_SCALE;
                    if (dg && (t * FN + nb * 8 + tq * 2 + e > row)) s = -1e30f;
                    sacc[nb][2 * hf + e] = s;
                    tm = fmaxf(tm, s);
                }
            }
            tm = fmaxf(tm, __shfl_xor_sync(0xffffffffu, tm, 1));
            tm = fmaxf(tm, __shfl_xor_sync(0xffffffffu, tm, 2));
            float mn = fmaxf(mst[hf], tm);
            float corr = __expf(mst[hf] - mn);
            mst[hf] = mn;
            float sum = 0.f;
#pragma unroll
            for (int nb = 0; nb < 8; nb++) {
#pragma unroll
                for (int e = 0; e < 2; e++) {
                    float p = __expf(sacc[nb][2 * hf + e] - mn);
                    sacc[nb][2 * hf + e] = p;
                    sum += p;
                }
            }
            sum += __shfl_xor_sync(0xffffffffu, sum, 1);
            sum += __shfl_xor_sync(0xffffffffu, sum, 2);
            lst[hf] = lst[hf] * corr + sum;
#pragma unroll
            for (int nb = 0; nb < 16; nb++) {
                oacc[nb][2 * hf + 0] *= corr;
                oacc[nb][2 * hf + 1] *= corr;
            }
        }

        // ---- pack P into bf16 hi/lo A-fragments ----
        uint32_t PH[2][8], PL[2][8];
#pragma unroll
        for (int nb = 0; nb < 8; nb++) {
#pragma unroll
            for (int hf = 0; hf < 2; hf++) {
                split2(sacc[nb][2 * hf], sacc[nb][2 * hf + 1],
                       PH[hf][nb], PL[hf][nb]);
            }
        }

        // ---- O += P V (3 passes fused) ----
#pragma unroll
        for (int kk = 0; kk < 4; kk++) {
            uint32_t ah[4] = {PH[0][2 * kk], PH[1][2 * kk],
                              PH[0][2 * kk + 1], PH[1][2 * kk + 1]};
            uint32_t al[4] = {PL[0][2 * kk], PL[1][2 * kk],
                              PL[0][2 * kk + 1], PL[1][2 * kk + 1]};
#pragma unroll
            for (int jj = 0; jj < 8; jj++) {
                int r = jj * 16 + (mat >> 1) * 8 + wi;
                int c16 = 2 * kk + (mat & 1);
                uint32_t v[4];
                LDMATRIX_X4(v[0], v[1], v[2], v[3],
                            st + SV_HI + r * 128 + ((c16 ^ (r & 7)) << 4));
                MMA_BF16(oacc[2 * jj], ah, v);
                MMA_BF16(oacc[2 * jj + 1], ah, (v + 2));
                MMA_BF16(oacc[2 * jj], al, v);
                MMA_BF16(oacc[2 * jj + 1], al, (v + 2));
                LDMATRIX_X4(v[0], v[1], v[2], v[3],
                            st + SV_LO + r * 128 + ((c16 ^ (r & 7)) << 4));
                MMA_BF16(oacc[2 * jj], ah, v);
                MMA_BF16(oacc[2 * jj + 1], ah, (v + 2));
            }
        }

        __syncthreads();
        if (t + 2 < ntiles) {
            issueKV(t + 2, t & 1);
            CP_COMMIT();
            CP_WAIT1();
        } else {
            CP_WAIT0();
        }
        __syncthreads();
    }

    // ---- epilogue: O/l -> bf16 hi/lo into gA ----
#pragma unroll
    for (int hf = 0; hf < 2; hf++) {
        float inv = 1.f / lst[hf];
        size_t row = bS + m0 + wm + g + hf * 8;
#pragma unroll
        for (int nb = 0; nb < 16; nb++) {
            float v0 = oacc[nb][2 * hf] * inv;
            float v1 = oacc[nb][2 * hf + 1] * inv;
            uint32_t hh, ll;
            split2(v0, v1, hh, ll);
            size_t off = row * HID_C + h * HEAD_D + nb * 8 + tq * 2;
            *(uint32_t*)&gA_hi[off] = hh;
            *(uint32_t*)&gA_lo[off] = ll;
        }
    }
}

// ---------------------------------------------------------------------------
extern "C" void kernel_launch(void* const* d_in, const int* in_sizes, int n_in,
                              void* d_out, int out_size)
{
    (void)in_sizes; (void)n_in; (void)out_size;
    const float* hs  = (const float*)d_in[0];
    /* d_in[1] = attention_mask (exact causal tril) applied analytically */
    const float* Wq  = (const float*)d_in[2];
    const float* bq  = (const float*)d_in[3];
    const float* Wkv = (const float*)d_in[4];
    const float* bkv = (const float*)d_in[5];
    const float* Wp  = (const float*)d_in[6];
    const float* bp  = (const float*)d_in[7];
    float* out = (float*)d_out;

    __nv_bfloat16 *pAhi, *pAlo, *pWqh, *pWql, *pWkh, *pWkl, *pWph, *pWpl;
    cudaGetSymbolAddress((void**)&pAhi, gA_hi);
    cudaGetSymbolAddress((void**)&pAlo, gA_lo);
    cudaGetSymbolAddress((void**)&pWqh, gWq_hi);
    cudaGetSymbolAddress((void**)&pWql, gWq_lo);
    cudaGetSymbolAddress((void**)&pWkh, gWkv_hi);
    cudaGetSymbolAddress((void**)&pWkl, gWkv_lo);
    cudaGetSymbolAddress((void**)&pWph, gWp_hi);
    cudaGetSymbolAddress((void**)&pWpl, gWp_lo);

    cudaFuncSetAttribute(mma_gemm_kernel,
                         cudaFuncAttributeMaxDynamicSharedMemorySize, GEMM_SMEM);
    cudaFuncSetAttribute(flash_mma_kernel,
                         cudaFuncAttributeMaxDynamicSharedMemorySize, FA_SMEM);

    // 1. split hidden states into bf16 hi/lo
    {
        int n4 = M_ROWS * HID_C / 4;
        split_f32_kernel<<<(n4 + 255) / 256, 256>>>(hs, pAhi, pAlo, n4);
    }
    // 2. transpose+split weights
    tconv_kernel<<<dim3(HID_C / 32, HID_C / 32), dim3(32, 8)>>>(Wq, pWqh, pWql, HID_C, HID_C);
    tconv_kernel<<<dim3(KV_C / 32, HID_C / 32), dim3(32, 8)>>>(Wkv, pWkh, pWkl, HID_C, KV_C);
    tconv_kernel<<<dim3(HID_C / 32, HID_C / 32), dim3(32, 8)>>>(Wp, pWph, pWpl, HID_C, HID_C);

    // 3. Q = hs @ Wq + bq  -> bf16 hi/lo (mode 1)
    mma_gemm_kernel<<<dim3(HID_C / BN, M_ROWS / BM), 256, GEMM_SMEM>>>(
        pAhi, pAlo, pWqh, pWql, bq, nullptr, HID_C, 1);
    // 4. KV = hs @ Wkv + bkv -> K hi/lo + V^T hi/lo (mode 2)
    mma_gemm_kernel<<<dim3(KV_C / BN, M_ROWS / BM), 256, GEMM_SMEM>>>(
        pAhi, pAlo, pWkh, pWkl, bkv, nullptr, KV_C, 2);
    // 5. attention (tensor cores) -> gA_hi/gA_lo
    flash_mma_kernel<<<dim3(S_LEN / FM, N_HEADS, B_SZ), 256, FA_SMEM>>>();
    // 6. out = attn @ Wp + bp (mode 0)
    mma_gemm_kernel<<<dim3(HID_C / BN, M_ROWS / BM), 256, GEMM_SMEM>>>(
        pAhi, pAlo, pWph, pWpl, bp, out, HID_C, 0);
}

// round 7
// speedup vs baseline: 2.7673x; 1.0321x over previous
#include <cuda_runtime.h>
#include <cuda_fp16.h>
#include <cstdint>

#define B_SZ 2
#define S_LEN 2048
#define HID_C 2048
#define N_HEADS 16
#define HEAD_D 128
#define M_ROWS (B_SZ * S_LEN)   /* 4096 */
#define KV_C 256

#define SOFTMAX_SCALE 0.08838834764831845f  /* 1/sqrt(128) */

// ---------------------------------------------------------------------------
// Device-global scratch (allocation-free rule)
// ---------------------------------------------------------------------------
__device__ __half gA_hi[(size_t)M_ROWS * HID_C];   // hs / attn hi (left operand)
__device__ __half gA_lo[(size_t)M_ROWS * HID_C];
__device__ __half gQhi[(size_t)M_ROWS * HID_C];
__device__ __half gQlo[(size_t)M_ROWS * HID_C];
__device__ __half gKhi[(size_t)M_ROWS * HEAD_D];          // right operand: hi only
__device__ __half gVthi[(size_t)HEAD_D * M_ROWS];         // V^T [d][bS], hi only
__device__ __half gWq_hi[(size_t)HID_C * HID_C];
__device__ __half gWkv_hi[(size_t)KV_C * HID_C];
__device__ __half gWp_hi[(size_t)HID_C * HID_C];

__device__ __forceinline__ uint32_t smem_to_u32(const void* p) {
    uint32_t a;
    asm("{ .reg .u64 t; cvta.to.shared.u64 t, %1; cvt.u32.u64 %0, t; }"
        : "=r"(a) : "l"(p));
    return a;
}

#define CP_ASYNC16(sm, g) \
    asm volatile("cp.async.cg.shared.global [%0], [%1], 16;" \
                 :: "r"(sm), "l"(g) : "memory")
#define CP_COMMIT() asm volatile("cp.async.commit_group;" ::: "memory")
#define CP_WAIT1()  asm volatile("cp.async.wait_group 1;" ::: "memory")
#define CP_WAIT0()  asm volatile("cp.async.wait_group 0;" ::: "memory")

#define LDMATRIX_X4(r0, r1, r2, r3, addr) \
    asm volatile("ldmatrix.sync.aligned.m8n8.x4.shared.b16 {%0,%1,%2,%3}, [%4];" \
                 : "=r"(r0), "=r"(r1), "=r"(r2), "=r"(r3) : "r"(addr))

#define MMA_F16(d, a, b) \
    asm volatile("mma.sync.aligned.m16n8k16.row.col.f32.f16.f16.f32 " \
                 "{%0,%1,%2,%3}, {%4,%5,%6,%7}, {%8,%9}, {%0,%1,%2,%3};" \
                 : "+f"((d)[0]), "+f"((d)[1]), "+f"((d)[2]), "+f"((d)[3]) \
                 : "r"((a)[0]), "r"((a)[1]), "r"((a)[2]), "r"((a)[3]), \
                   "r"((b)[0]), "r"((b)[1]))

__device__ __forceinline__ uint32_t pack_h2(__half x, __half y) {
    __half2 t; t.x = x; t.y = y;
    return *reinterpret_cast<uint32_t*>(&t);
}
// fp32 pair -> fp16 hi + fp16 lo(residual)
__device__ __forceinline__ void split2h(float v0, float v1,
                                        uint32_t& hi, uint32_t& lo) {
    __half h0 = __float2half_rn(v0);
    __half h1 = __float2half_rn(v1);
    hi = pack_h2(h0, h1);
    lo = pack_h2(__float2half_rn(v0 - __half2float(h0)),
                 __float2half_rn(v1 - __half2float(h1)));
}

// ---------------------------------------------------------------------------
// fp32 -> (hi, lo) fp16 split, elementwise
// ---------------------------------------------------------------------------
__global__ void split_f32_kernel(const float* __restrict__ src,
                                 __half* __restrict__ hi,
                                 __half* __restrict__ lo, int n4)
{
    int i = blockIdx.x * blockDim.x + threadIdx.x;
    if (i >= n4) return;
    float4 v = ((const float4*)src)[i];
    uint32_t h0, l0, h1, l1;
    split2h(v.x, v.y, h0, l0);
    split2h(v.z, v.w, h1, l1);
    ((uint32_t*)hi)[2 * i] = h0;
    ((uint32_t*)hi)[2 * i + 1] = h1;
    ((uint32_t*)lo)[2 * i] = l0;
    ((uint32_t*)lo)[2 * i + 1] = l1;
}

// ---------------------------------------------------------------------------
// W[K][N] f32 -> Wt_hi[N][K] fp16 (transpose, hi only — right operand)
// ---------------------------------------------------------------------------
__global__ void tconv_kernel(const float* __restrict__ W,
                             __half* __restrict__ Thi, int K, int N)
{
    __shared__ float tile[32][33];
    int n0 = blockIdx.x * 32, k0 = blockIdx.y * 32;
    int tx = threadIdx.x, ty = threadIdx.y;
#pragma unroll
    for (int j = 0; j < 32; j += 8)
        tile[ty + j][tx] = W[(size_t)(k0 + ty + j) * N + n0 + tx];
    __syncthreads();
#pragma unroll
    for (int j = 0; j < 32; j += 8)
        Thi[(size_t)(n0 + ty + j) * K + k0 + tx] = __float2half_rn(tile[tx][ty + j]);
}

// ---------------------------------------------------------------------------
// mma.sync fp16 GEMM: C = (Ah+Al) @ Bh^T + bias   (2-product emulation)
// mode 0: out-proj -> fp32 C (B0 = Wp)
// mode 1: fused QKV: bx<16 -> Q (B0=Wq) split-> gQhi/gQlo
//                    bx>=16 -> KV (B1=Wkv): bn==0 -> K hi; bn==128 -> V^T hi
// ---------------------------------------------------------------------------
#define BM 128
#define BN 128
#define BKH 32                  /* halves per chunk */
#define APITCH_B 80
#define STG_A (BM * APITCH_B)
#define STG_B (BN * APITCH_B)
#define STG_BYTES (STG_A + STG_B)
#define NSTAGE 3
#define GEMM_SMEM (NSTAGE * STG_BYTES)
#define NCHUNK 128              /* 2 phases * 64 chunks */

__global__ __launch_bounds__(256, 2)
void mma_gemm_kernel(const __half* __restrict__ Ahi,
                     const __half* __restrict__ Alo,
                     const __half* __restrict__ B0,
                     const float* __restrict__ bias0,
                     const __half* __restrict__ B1,
                     const float* __restrict__ bias1,
                     float* __restrict__ C, int N, int mode)
{
    extern __shared__ char smem[];
    const uint32_t smem_base = smem_to_u32(smem);
    const int tid = threadIdx.x;
    const int wid = tid >> 5;
    const int lid = tid & 31;
    const int bm = blockIdx.y * BM;
    const bool isKV = (mode == 1) && (blockIdx.x >= 16);
    const int bn = isKV ? (blockIdx.x - 16) * BN : blockIdx.x * BN;
    const __half* Bh = isKV ? B1 : B0;
    const float* bias = isKV ? bias1 : bias0;

    auto issue = [&](int c, int stage) {
        const __half* Asrc = (c >> 6) ? Alo : Ahi;
        const size_t k0 = (size_t)(c & 63) * BKH;
        const uint32_t sA = smem_base + stage * STG_BYTES;
        const uint32_t sB = sA + STG_A;
#pragma unroll
        for (int j = 0; j < 2; j++) {
            int seg = tid + j * 256;
            int r = seg >> 2, s = seg & 3;
            CP_ASYNC16(sA + r * APITCH_B + s * 16,
                       (const char*)(Asrc + (size_t)(bm + r) * HID_C + k0 + s * 8));
        }
#pragma unroll
        for (int j = 0; j < 2; j++) {
            int seg = tid + j * 256;
            int r = seg >> 2, s = seg & 3;
            CP_ASYNC16(sB + r * APITCH_B + s * 16,
                       (const char*)(Bh + (size_t)(bn + r) * HID_C + k0 + s * 8));
        }
    };

    float acc[4][4][4];
#pragma unroll
    for (int i = 0; i < 4; i++)
#pragma unroll
        for (int j = 0; j < 4; j++)
#pragma unroll
            for (int q = 0; q < 4; q++) acc[i][j][q] = 0.f;

    issue(0, 0); CP_COMMIT();
    issue(1, 1); CP_COMMIT();

    const int wm = (wid >> 2) * 64;
    const int wn = (wid & 3) * 32;
    const int mat = lid >> 3;
    const int wi = lid & 7;

    for (int t = 0; t < NCHUNK; t++) {
        CP_WAIT1();
        __syncthreads();
        if (t + 2 < NCHUNK) issue(t + 2, (t + 2) % NSTAGE);
        CP_COMMIT();

        const uint32_t aBase = smem_base + (t % NSTAGE) * STG_BYTES;
        const uint32_t bBase = aBase + STG_A;
#pragma unroll
        for (int ks = 0; ks < 2; ks++) {
            const int k0 = ks * 16;
            uint32_t afr[4][4];
            uint32_t bfr[4][2];
#pragma unroll
            for (int i = 0; i < 4; i++) {
                int row = wm + i * 16 + (mat & 1) * 8 + wi;
                int col = k0 + (mat >> 1) * 8;
                LDMATRIX_X4(afr[i][0], afr[i][1], afr[i][2], afr[i][3],
                            aBase + row * APITCH_B + col * 2);
            }
#pragma unroll
            for (int jj = 0; jj < 2; jj++) {
                int n = wn + jj * 16 + (mat >> 1) * 8 + wi;
                int k = k0 + (mat & 1) * 8;
                LDMATRIX_X4(bfr[2 * jj][0], bfr[2 * jj][1],
                            bfr[2 * jj + 1][0], bfr[2 * jj + 1][1],
                            bBase + n * APITCH_B + k * 2);
            }
#pragma unroll
            for (int i = 0; i < 4; i++)
#pragma unroll
                for (int j = 0; j < 4; j++)
                    MMA_F16(acc[i][j], afr[i], bfr[j]);
        }
    }

    const int g = lid >> 2;
    const int tq = lid & 3;
#pragma unroll
    for (int i = 0; i < 4; i++) {
#pragma unroll
        for (int j = 0; j < 4; j++) {
            int row0 = bm + wm + i * 16 + g;
            int col = bn + wn + j * 8 + tq * 2;
            float b0 = bias[col], b1 = bias[col + 1];
            float v00 = acc[i][j][0] + b0, v01 = acc[i][j][1] + b1;
            float v10 = acc[i][j][2] + b0, v11 = acc[i][j][3] + b1;
            if (mode == 0) {
                *(float2*)(C + (size_t)row0 * N + col) = make_float2(v00, v01);
                *(float2*)(C + (size_t)(row0 + 8) * N + col) = make_float2(v10, v11);
            } else if (!isKV) {   // Q: split into hi/lo fp16
                uint32_t h, l;
                split2h(v00, v01, h, l);
                *(uint32_t*)&gQhi[(size_t)row0 * HID_C + col] = h;
                *(uint32_t*)&gQlo[(size_t)row0 * HID_C + col] = l;
                split2h(v10, v11, h, l);
                *(uint32_t*)&gQhi[(size_t)(row0 + 8) * HID_C + col] = h;
                *(uint32_t*)&gQlo[(size_t)(row0 + 8) * HID_C + col] = l;
            } else {
                if (bn == 0) {    // K: hi only
                    *(uint32_t*)&gKhi[(size_t)row0 * HEAD_D + col] =
                        pack_h2(__float2half_rn(v00), __float2half_rn(v01));
                    *(uint32_t*)&gKhi[(size_t)(row0 + 8) * HEAD_D + col] =
                        pack_h2(__float2half_rn(v10), __float2half_rn(v11));
                } else {          // V: transpose, hi only
                    int d0 = col - 128;
                    float vs[2][2] = {{v00, v01}, {v10, v11}};
#pragma unroll
                    for (int rr = 0; rr < 2; rr++)
#pragma unroll
                        for (int cc = 0; cc < 2; cc++)
                            gVthi[(size_t)(d0 + cc) * M_ROWS + row0 + rr * 8] =
                                __float2half_rn(vs[rr][cc]);
                }
            }
        }
    }
}

// ---------------------------------------------------------------------------
// Flash attention, tensor-core fp16, 2-product emulation, causal.
// CTA: 128 q-rows x (head, batch); 8 warps (m16); KV tile 64.
// Smem: Q hi/lo [128][128]h + 2 stages {K hi [64][128]h, Vt hi [128][64]h}
// ---------------------------------------------------------------------------
#define FM 128
#define FN 64
#define SMQ_HI 0
#define SMQ_LO 32768
#define SM_STG 65536
#define STGSZ 32768
#define SK_OFF 0
#define SV_OFF 16384
#define FA_SMEM (65536 + 2 * STGSZ)   /* 131072 */

__global__ __launch_bounds__(256, 1)
void flash_mma_kernel()
{
    extern __shared__ char sm[];
    const uint32_t sb = smem_to_u32(sm);
    const int tid = threadIdx.x;
    const int wid = tid >> 5;
    const int lid = tid & 31;
    const int qt = (int)gridDim.x - 1 - (int)blockIdx.x;
    const int h = blockIdx.y;
    const int b = blockIdx.z;
    const int m0 = qt * FM;
    const int wm = wid * 16;
    const size_t bS = (size_t)b * S_LEN;
    const int g = lid >> 2, tq = lid & 3;
    const int ntiles = 2 * qt + 2;

    auto issueQ = [&]() {
#pragma unroll
        for (int j = 0; j < 16; j++) {
            int idx = tid + j * 256;
            int arr = idx >> 11;
            int rem = idx & 2047;
            int r = rem >> 4, c16 = rem & 15;
            const __half* src =
                (arr ? gQlo : gQhi) + (bS + m0 + r) * HID_C + h * HEAD_D + c16 * 8;
            CP_ASYNC16(sb + (arr ? SMQ_LO : SMQ_HI) + r * 256 + ((c16 ^ (r & 7)) << 4),
                       (const char*)src);
        }
    };
    auto issueKV = [&](int t, int s) {
        const uint32_t st = sb + SM_STG + s * STGSZ;
        const int n0 = t * FN;
#pragma unroll
        for (int j = 0; j < 4; j++) {
            int idx = tid + j * 256;
            int r = idx >> 4, c16 = idx & 15;
            const __half* src = gKhi + (bS + n0 + r) * HEAD_D + c16 * 8;
            CP_ASYNC16(st + SK_OFF + r * 256 + ((c16 ^ (r & 7)) << 4),
                       (const char*)src);
        }
#pragma unroll
        for (int j = 0; j < 4; j++) {
            int idx = tid + j * 256;
            int r = idx >> 3, c16 = idx & 7;
            const __half* src = gVthi + (size_t)r * M_ROWS + bS + n0 + c16 * 8;
            CP_ASYNC16(st + SV_OFF + r * 128 + ((c16 ^ (r & 7)) << 4),
                       (const char*)src);
        }
    };

    issueQ();
    issueKV(0, 0);
    CP_COMMIT();
    issueKV(1, 1);
    CP_COMMIT();
    CP_WAIT1();
    __syncthreads();

    float oacc[16][4];
#pragma unroll
    for (int i = 0; i < 16; i++)
#pragma unroll
        for (int q = 0; q < 4; q++) oacc[i][q] = 0.f;
    float mst[2] = {-1e30f, -1e30f};
    float lst[2] = {0.f, 0.f};

    const int mat = lid >> 3;
    const int wi = lid & 7;

    for (int t = 0; t < ntiles; t++) {
        const uint32_t st = sb + SM_STG + (t & 1) * STGSZ;

        // ---- S = (Qh + Ql) K^T : 2 passes ----
        float sacc[8][4];
#pragma unroll
        for (int i = 0; i < 8; i++)
#pragma unroll
            for (int q = 0; q < 4; q++) sacc[i][q] = 0.f;

#pragma unroll
        for (int pass = 0; pass < 2; pass++) {
            const uint32_t qb = sb + (pass ? SMQ_LO : SMQ_HI);
            const uint32_t kb = st + SK_OFF;
#pragma unroll
            for (int kk = 0; kk < 8; kk++) {
                uint32_t a[4];
                {
                    int r = wm + (lid & 15);
                    int c16 = 2 * kk + (lid >> 4);
                    LDMATRIX_X4(a[0], a[1], a[2], a[3],
                                qb + r * 256 + ((c16 ^ (r & 7)) << 4));
                }
                uint32_t bf[8][2];
#pragma unroll
                for (int jj = 0; jj < 4; jj++) {
                    int r = jj * 16 + (mat >> 1) * 8 + wi;
                    int c16 = 2 * kk + (mat & 1);
                    LDMATRIX_X4(bf[2 * jj][0], bf[2 * jj][1],
                                bf[2 * jj + 1][0], bf[2 * jj + 1][1],
                                kb + r * 256 + ((c16 ^ (r & 7)) << 4));
                }
#pragma unroll
                for (int nb = 0; nb < 8; nb++)
                    MMA_F16(sacc[nb], a, bf[nb]);
            }
        }

        // ---- online softmax ----
        const bool dg = (t >= 2 * qt);
#pragma unroll
        for (int hf = 0; hf < 2; hf++) {
            const int row = m0 + wm + g + hf * 8;
            float tm = -1e30f;
#pragma unroll
            for (int nb = 0; nb < 8; nb++) {
#pragma unroll
                for (int e = 0; e < 2; e++) {
                    float s = sacc[nb][2 * hf + e] * SOFTMAX_SCALE;
                    if (dg && (t * FN + nb * 8 + tq * 2 + e > row)) s = -1e30f;
                    sacc[nb][2 * hf + e] = s;
                    tm = fmaxf(tm, s);
                }
            }
            tm = fmaxf(tm, __shfl_xor_sync(0xffffffffu, tm, 1));
            tm = fmaxf(tm, __shfl_xor_sync(0xffffffffu, tm, 2));
            float mn = fmaxf(mst[hf], tm);
            float corr = __expf(mst[hf] - mn);
            mst[hf] = mn;
            float sum = 0.f;
#pragma unroll
            for (int nb = 0; nb < 8; nb++) {
#pragma unroll
                for (int e = 0; e < 2; e++) {
                    float p = __expf(sacc[nb][2 * hf + e] - mn);
                    sacc[nb][2 * hf + e] = p;
                    sum += p;
                }
            }
            sum += __shfl_xor_sync(0xffffffffu, sum, 1);
            sum += __shfl_xor_sync(0xffffffffu, sum, 2);
            lst[hf] = lst[hf] * corr + sum;
#pragma unroll
            for (int nb = 0; nb < 16; nb++) {
                oacc[nb][2 * hf + 0] *= corr;
                oacc[nb][2 * hf + 1] *= corr;
            }
        }

        // ---- P -> fp16 hi/lo A-fragments (in-register) ----
        uint32_t PH[2][8], PL[2][8];
#pragma unroll
        for (int nb = 0; nb < 8; nb++)
#pragma unroll
            for (int hf = 0; hf < 2; hf++)
                split2h(sacc[nb][2 * hf], sacc[nb][2 * hf + 1],
                        PH[hf][nb], PL[hf][nb]);

        // ---- O += (Ph + Pl) Vh ----
#pragma unroll
        for (int kk = 0; kk < 4; kk++) {
            uint32_t ah[4] = {PH[0][2 * kk], PH[1][2 * kk],
                              PH[0][2 * kk + 1], PH[1][2 * kk + 1]};
            uint32_t al[4] = {PL[0][2 * kk], PL[1][2 * kk],
                              PL[0][2 * kk + 1], PL[1][2 * kk + 1]};
#pragma unroll
            for (int jj = 0; jj < 8; jj++) {
                int r = jj * 16 + (mat >> 1) * 8 + wi;
                int c16 = 2 * kk + (mat & 1);
                uint32_t v[4];
                LDMATRIX_X4(v[0], v[1], v[2], v[3],
                            st + SV_OFF + r * 128 + ((c16 ^ (r & 7)) << 4));
                MMA_F16(oacc[2 * jj], ah, v);
                MMA_F16(oacc[2 * jj + 1], ah, (v + 2));
                MMA_F16(oacc[2 * jj], al, v);
                MMA_F16(oacc[2 * jj + 1], al, (v + 2));
            }
        }

        __syncthreads();
        if (t + 2 < ntiles) {
            issueKV(t + 2, t & 1);
            CP_COMMIT();
            CP_WAIT1();
        } else {
            CP_WAIT0();
        }
        __syncthreads();
    }

    // ---- epilogue: O/l -> fp16 hi/lo into gA ----
#pragma unroll
    for (int hf = 0; hf < 2; hf++) {
        float inv = 1.f / lst[hf];
        size_t row = bS + m0 + wm + g + hf * 8;
#pragma unroll
        for (int nb = 0; nb < 16; nb++) {
            float v0 = oacc[nb][2 * hf] * inv;
            float v1 = oacc[nb][2 * hf + 1] * inv;
            uint32_t hh, ll;
            split2h(v0, v1, hh, ll);
            size_t off = row * HID_C + h * HEAD_D + nb * 8 + tq * 2;
            *(uint32_t*)&gA_hi[off] = hh;
            *(uint32_t*)&gA_lo[off] = ll;
        }
    }
}

// ---------------------------------------------------------------------------
extern "C" void kernel_launch(void* const* d_in, const int* in_sizes, int n_in,
                              void* d_out, int out_size)
{
    (void)in_sizes; (void)n_in; (void)out_size;
    const float* hs  = (const float*)d_in[0];
    /* d_in[1] = attention_mask (exact causal tril) applied analytically */
    const float* Wq  = (const float*)d_in[2];
    const float* bq  = (const float*)d_in[3];
    const float* Wkv = (const float*)d_in[4];
    const float* bkv = (const float*)d_in[5];
    const float* Wp  = (const float*)d_in[6];
    const float* bp  = (const float*)d_in[7];
    float* out = (float*)d_out;

    __half *pAhi, *pAlo, *pWqh, *pWkh, *pWph;
    cudaGetSymbolAddress((void**)&pAhi, gA_hi);
    cudaGetSymbolAddress((void**)&pAlo, gA_lo);
    cudaGetSymbolAddress((void**)&pWqh, gWq_hi);
    cudaGetSymbolAddress((void**)&pWkh, gWkv_hi);
    cudaGetSymbolAddress((void**)&pWph, gWp_hi);

    cudaFuncSetAttribute(mma_gemm_kernel,
                         cudaFuncAttributeMaxDynamicSharedMemorySize, GEMM_SMEM);
    cudaFuncSetAttribute(flash_mma_kernel,
                         cudaFuncAttributeMaxDynamicSharedMemorySize, FA_SMEM);

    // 1. split hidden states into fp16 hi/lo
    {
        int n4 = M_ROWS * HID_C / 4;
        split_f32_kernel<<<(n4 + 255) / 256, 256>>>(hs, pAhi, pAlo, n4);
    }
    // 2. transpose+convert weights (hi only)
    tconv_kernel<<<dim3(HID_C / 32, HID_C / 32), dim3(32, 8)>>>(Wq, pWqh, HID_C, HID_C);
    tconv_kernel<<<dim3(KV_C / 32, HID_C / 32), dim3(32, 8)>>>(Wkv, pWkh, HID_C, KV_C);
    tconv_kernel<<<dim3(HID_C / 32, HID_C / 32), dim3(32, 8)>>>(Wp, pWph, HID_C, HID_C);

    // 3. fused Q + KV projection (grid.x: 16 Q blocks + 2 KV blocks)
    mma_gemm_kernel<<<dim3(18, M_ROWS / BM), 256, GEMM_SMEM>>>(
        pAhi, pAlo, pWqh, bq, pWkh, bkv, nullptr, HID_C, 1);
    // 4. attention -> gA_hi/gA_lo
    flash_mma_kernel<<<dim3(S_LEN / FM, N_HEADS, B_SZ), 256, FA_SMEM>>>();
    // 5. out = attn @ Wp + bp
    mma_gemm_kernel<<<dim3(16, M_ROWS / BM), 256, GEMM_SMEM>>>(
        pAhi, pAlo, pWph, bp, nullptr, nullptr, out, HID_C, 0);
}

// round 8
// speedup vs baseline: 4.3872x; 1.5853x over previous
#include <cuda_runtime.h>
#include <cuda_fp16.h>
#include <cstdint>

#define B_SZ 2
#define S_LEN 2048
#define HID_C 2048
#define N_HEADS 16
#define HEAD_D 128
#define M_ROWS (B_SZ * S_LEN)   /* 4096 */
#define KV_C 256

#define SOFTMAX_SCALE 0.08838834764831845f            /* 1/sqrt(128) */
#define SOFTMAX_SCALE_LOG2 0.12754404735576283f       /* 1/sqrt(128)*log2(e) */

// ---------------------------------------------------------------------------
// Device-global scratch (allocation-free rule)
// ---------------------------------------------------------------------------
__device__ __half gA_hi[(size_t)M_ROWS * HID_C];   // hs / attn hi (left operand)
__device__ __half gA_lo[(size_t)M_ROWS * HID_C];
__device__ __half gQhi[(size_t)M_ROWS * HID_C];
__device__ __half gQlo[(size_t)M_ROWS * HID_C];
__device__ __half gKhi[(size_t)M_ROWS * HEAD_D];          // right operand: hi only
__device__ __half gVthi[(size_t)HEAD_D * M_ROWS];         // V^T [d][bS], hi only
__device__ __half gWq_hi[(size_t)HID_C * HID_C];
__device__ __half gWkv_hi[(size_t)KV_C * HID_C];
__device__ __half gWp_hi[(size_t)HID_C * HID_C];

__device__ __forceinline__ uint32_t smem_to_u32(const void* p) {
    uint32_t a;
    asm("{ .reg .u64 t; cvta.to.shared.u64 t, %1; cvt.u32.u64 %0, t; }"
        : "=r"(a) : "l"(p));
    return a;
}

#define CP_ASYNC16(sm, g) \
    asm volatile("cp.async.cg.shared.global [%0], [%1], 16;" \
                 :: "r"(sm), "l"(g) : "memory")
#define CP_COMMIT() asm volatile("cp.async.commit_group;" ::: "memory")
#define CP_WAIT1()  asm volatile("cp.async.wait_group 1;" ::: "memory")
#define CP_WAIT0()  asm volatile("cp.async.wait_group 0;" ::: "memory")

#define LDMATRIX_X4(r0, r1, r2, r3, addr) \
    asm volatile("ldmatrix.sync.aligned.m8n8.x4.shared.b16 {%0,%1,%2,%3}, [%4];" \
                 : "=r"(r0), "=r"(r1), "=r"(r2), "=r"(r3) : "r"(addr))

#define MMA_F16(d, a, b) \
    asm volatile("mma.sync.aligned.m16n8k16.row.col.f32.f16.f16.f32 " \
                 "{%0,%1,%2,%3}, {%4,%5,%6,%7}, {%8,%9}, {%0,%1,%2,%3};" \
                 : "+f"((d)[0]), "+f"((d)[1]), "+f"((d)[2]), "+f"((d)[3]) \
                 : "r"((a)[0]), "r"((a)[1]), "r"((a)[2]), "r"((a)[3]), \
                   "r"((b)[0]), "r"((b)[1]))

__device__ __forceinline__ uint32_t pack_h2(__half x, __half y) {
    __half2 t; t.x = x; t.y = y;
    return *reinterpret_cast<uint32_t*>(&t);
}
// fp32 pair -> fp16 hi + fp16 lo(residual)
__device__ __forceinline__ void split2h(float v0, float v1,
                                        uint32_t& hi, uint32_t& lo) {
    __half h0 = __float2half_rn(v0);
    __half h1 = __float2half_rn(v1);
    hi = pack_h2(h0, h1);
    lo = pack_h2(__float2half_rn(v0 - __half2float(h0)),
                 __float2half_rn(v1 - __half2float(h1)));
}

// ---------------------------------------------------------------------------
// fp32 -> (hi, lo) fp16 split, elementwise
// ---------------------------------------------------------------------------
__global__ void split_f32_kernel(const float* __restrict__ src,
                                 __half* __restrict__ hi,
                                 __half* __restrict__ lo, int n4)
{
    int i = blockIdx.x * blockDim.x + threadIdx.x;
    if (i >= n4) return;
    float4 v = ((const float4*)src)[i];
    uint32_t h0, l0, h1, l1;
    split2h(v.x, v.y, h0, l0);
    split2h(v.z, v.w, h1, l1);
    ((uint32_t*)hi)[2 * i] = h0;
    ((uint32_t*)hi)[2 * i + 1] = h1;
    ((uint32_t*)lo)[2 * i] = l0;
    ((uint32_t*)lo)[2 * i + 1] = l1;
}

// ---------------------------------------------------------------------------
// Fused weight transpose+convert: z=0 Wq, z=1 Wp, z=2 Wkv
// ---------------------------------------------------------------------------
__global__ void tconv_all_kernel(const float* __restrict__ Wq,
                                 const float* __restrict__ Wp,
                                 const float* __restrict__ Wkv)
{
    const int z = blockIdx.z;
    const float* W = (z == 0) ? Wq : (z == 1) ? Wp : Wkv;
    __half* T = (z == 0) ? gWq_hi : (z == 1) ? gWp_hi : gWkv_hi;
    const int N = (z == 2) ? KV_C : HID_C;
    if (blockIdx.x * 32 >= N) return;

    __shared__ float tile[32][33];
    int n0 = blockIdx.x * 32, k0 = blockIdx.y * 32;
    int tx = threadIdx.x, ty = threadIdx.y;
#pragma unroll
    for (int j = 0; j < 32; j += 8)
        tile[ty + j][tx] = W[(size_t)(k0 + ty + j) * N + n0 + tx];
    __syncthreads();
#pragma unroll
    for (int j = 0; j < 32; j += 8)
        T[(size_t)(n0 + ty + j) * HID_C + k0 + tx] =
            __float2half_rn(tile[tx][ty + j]);
}

// ---------------------------------------------------------------------------
// mma.sync fp16 GEMM: C = (Ah+Al) @ Bh^T + bias   (2-product emulation)
// mode 0: out-proj -> fp32 C (B0 = Wp)
// mode 1: fused QKV: bx<16 -> Q (B0=Wq) split-> gQhi/gQlo
//                    bx>=16 -> KV (B1=Wkv): bn==0 -> K hi; bn==128 -> V^T hi
// ---------------------------------------------------------------------------
#define BM 128
#define BN 128
#define BKH 32                  /* halves per chunk */
#define APITCH_B 80
#define STG_A (BM * APITCH_B)
#define STG_B (BN * APITCH_B)
#define STG_BYTES (STG_A + STG_B)
#define NSTAGE 3
#define GEMM_SMEM (NSTAGE * STG_BYTES)
#define NCHUNK 128              /* 2 phases * 64 chunks */

__global__ __launch_bounds__(256, 2)
void mma_gemm_kernel(const __half* __restrict__ Ahi,
                     const __half* __restrict__ Alo,
                     const __half* __restrict__ B0,
                     const float* __restrict__ bias0,
                     const __half* __restrict__ B1,
                     const float* __restrict__ bias1,
                     float* __restrict__ C, int N, int mode)
{
    extern __shared__ char smem[];
    const uint32_t smem_base = smem_to_u32(smem);
    const int tid = threadIdx.x;
    const int wid = tid >> 5;
    const int lid = tid & 31;
    const int bm = blockIdx.y * BM;
    const bool isKV = (mode == 1) && (blockIdx.x >= 16);
    const int bn = isKV ? (blockIdx.x - 16) * BN : blockIdx.x * BN;
    const __half* Bh = isKV ? B1 : B0;
    const float* bias = isKV ? bias1 : bias0;

    auto issue = [&](int c, int stage) {
        const __half* Asrc = (c >> 6) ? Alo : Ahi;
        const size_t k0 = (size_t)(c & 63) * BKH;
        const uint32_t sA = smem_base + stage * STG_BYTES;
        const uint32_t sB = sA + STG_A;
#pragma unroll
        for (int j = 0; j < 2; j++) {
            int seg = tid + j * 256;
            int r = seg >> 2, s = seg & 3;
            CP_ASYNC16(sA + r * APITCH_B + s * 16,
                       (const char*)(Asrc + (size_t)(bm + r) * HID_C + k0 + s * 8));
        }
#pragma unroll
        for (int j = 0; j < 2; j++) {
            int seg = tid + j * 256;
            int r = seg >> 2, s = seg & 3;
            CP_ASYNC16(sB + r * APITCH_B + s * 16,
                       (const char*)(Bh + (size_t)(bn + r) * HID_C + k0 + s * 8));
        }
    };

    float acc[4][4][4];
#pragma unroll
    for (int i = 0; i < 4; i++)
#pragma unroll
        for (int j = 0; j < 4; j++)
#pragma unroll
            for (int q = 0; q < 4; q++) acc[i][j][q] = 0.f;

    issue(0, 0); CP_COMMIT();
    issue(1, 1); CP_COMMIT();

    const int wm = (wid >> 2) * 64;
    const int wn = (wid & 3) * 32;
    const int mat = lid >> 3;
    const int wi = lid & 7;

    for (int t = 0; t < NCHUNK; t++) {
        CP_WAIT1();
        __syncthreads();
        if (t + 2 < NCHUNK) issue(t + 2, (t + 2) % NSTAGE);
        CP_COMMIT();

        const uint32_t aBase = smem_base + (t % NSTAGE) * STG_BYTES;
        const uint32_t bBase = aBase + STG_A;
#pragma unroll
        for (int ks = 0; ks < 2; ks++) {
            const int k0 = ks * 16;
            uint32_t afr[4][4];
            uint32_t bfr[4][2];
#pragma unroll
            for (int i = 0; i < 4; i++) {
                int row = wm + i * 16 + (mat & 1) * 8 + wi;
                int col = k0 + (mat >> 1) * 8;
                LDMATRIX_X4(afr[i][0], afr[i][1], afr[i][2], afr[i][3],
                            aBase + row * APITCH_B + col * 2);
            }
#pragma unroll
            for (int jj = 0; jj < 2; jj++) {
                int n = wn + jj * 16 + (mat >> 1) * 8 + wi;
                int k = k0 + (mat & 1) * 8;
                LDMATRIX_X4(bfr[2 * jj][0], bfr[2 * jj][1],
                            bfr[2 * jj + 1][0], bfr[2 * jj + 1][1],
                            bBase + n * APITCH_B + k * 2);
            }
#pragma unroll
            for (int i = 0; i < 4; i++)
#pragma unroll
                for (int j = 0; j < 4; j++)
                    MMA_F16(acc[i][j], afr[i], bfr[j]);
        }
    }

    const int g = lid >> 2;
    const int tq = lid & 3;
#pragma unroll
    for (int i = 0; i < 4; i++) {
#pragma unroll
        for (int j = 0; j < 4; j++) {
            int row0 = bm + wm + i * 16 + g;
            int col = bn + wn + j * 8 + tq * 2;
            float b0 = bias[col], b1 = bias[col + 1];
            float v00 = acc[i][j][0] + b0, v01 = acc[i][j][1] + b1;
            float v10 = acc[i][j][2] + b0, v11 = acc[i][j][3] + b1;
            if (mode == 0) {
                *(float2*)(C + (size_t)row0 * N + col) = make_float2(v00, v01);
                *(float2*)(C + (size_t)(row0 + 8) * N + col) = make_float2(v10, v11);
            } else if (!isKV) {   // Q: split into hi/lo fp16
                uint32_t h, l;
                split2h(v00, v01, h, l);
                *(uint32_t*)&gQhi[(size_t)row0 * HID_C + col] = h;
                *(uint32_t*)&gQlo[(size_t)row0 * HID_C + col] = l;
                split2h(v10, v11, h, l);
                *(uint32_t*)&gQhi[(size_t)(row0 + 8) * HID_C + col] = h;
                *(uint32_t*)&gQlo[(size_t)(row0 + 8) * HID_C + col] = l;
            } else {
                if (bn == 0) {    // K: hi only
                    *(uint32_t*)&gKhi[(size_t)row0 * HEAD_D + col] =
                        pack_h2(__float2half_rn(v00), __float2half_rn(v01));
                    *(uint32_t*)&gKhi[(size_t)(row0 + 8) * HEAD_D + col] =
                        pack_h2(__float2half_rn(v10), __float2half_rn(v11));
                } else {          // V: transpose, hi only
                    int d0 = col - 128;
                    float vs[2][2] = {{v00, v01}, {v10, v11}};
#pragma unroll
                    for (int rr = 0; rr < 2; rr++)
#pragma unroll
                        for (int cc = 0; cc < 2; cc++)
                            gVthi[(size_t)(d0 + cc) * M_ROWS + row0 + rr * 8] =
                                __float2half_rn(vs[rr][cc]);
                }
            }
        }
    }
}

// ---------------------------------------------------------------------------
// Flash attention, tensor-core fp16, 2-product emulation on Q/P, causal.
// CTA: 128 q-rows x (head, batch); 8 warps (m16); KV tile FN=128.
// Smem: Q hi/lo [128][128]h (64KB) + 2 stages {K [128][128]h, Vt [128][128]h}
// ---------------------------------------------------------------------------
#define FM 128
#define FN 128
#define SMQ_HI 0
#define SMQ_LO 32768
#define SM_STG 65536
#define STGSZ 65536
#define SK_OFF 0
#define SV_OFF 32768
#define FA_SMEM (65536 + 2 * STGSZ)   /* 196608 */

__global__ __launch_bounds__(256, 1)
void flash_mma_kernel()
{
    extern __shared__ char sm[];
    const uint32_t sb = smem_to_u32(sm);
    const int tid = threadIdx.x;
    const int wid = tid >> 5;
    const int lid = tid & 31;
    const int qt = (int)gridDim.x - 1 - (int)blockIdx.x;  // heavy blocks first
    const int h = blockIdx.y;
    const int b = blockIdx.z;
    const int m0 = qt * FM;
    const int wm = wid * 16;
    const size_t bS = (size_t)b * S_LEN;
    const int g = lid >> 2, tq = lid & 3;
    const int ntiles = qt + 1;

    auto issueQ = [&]() {
#pragma unroll
        for (int j = 0; j < 16; j++) {
            int idx = tid + j * 256;
            int arr = idx >> 11;
            int rem = idx & 2047;
            int r = rem >> 4, c16 = rem & 15;
            const __half* src =
                (arr ? gQlo : gQhi) + (bS + m0 + r) * HID_C + h * HEAD_D + c16 * 8;
            CP_ASYNC16(sb + (arr ? SMQ_LO : SMQ_HI) + r * 256 + ((c16 ^ (r & 7)) << 4),
                       (const char*)src);
        }
    };
    auto issueKV = [&](int t, int s) {
        const uint32_t st = sb + SM_STG + s * STGSZ;
        const int n0 = t * FN;
#pragma unroll
        for (int j = 0; j < 8; j++) {
            int idx = tid + j * 256;
            int r = idx >> 4, c16 = idx & 15;
            const __half* src = gKhi + (bS + n0 + r) * HEAD_D + c16 * 8;
            CP_ASYNC16(st + SK_OFF + r * 256 + ((c16 ^ (r & 7)) << 4),
                       (const char*)src);
        }
#pragma unroll
        for (int j = 0; j < 8; j++) {
            int idx = tid + j * 256;
            int r = idx >> 4, c16 = idx & 15;
            const __half* src = gVthi + (size_t)r * M_ROWS + bS + n0 + c16 * 8;
            CP_ASYNC16(st + SV_OFF + r * 256 + ((c16 ^ (r & 7)) << 4),
                       (const char*)src);
        }
    };

    issueQ();
    issueKV(0, 0);
    CP_COMMIT();
    if (ntiles > 1) issueKV(1, 1);
    CP_COMMIT();
    CP_WAIT1();
    __syncthreads();

    float oacc[16][4];
#pragma unroll
    for (int i = 0; i < 16; i++)
#pragma unroll
        for (int q = 0; q < 4; q++) oacc[i][q] = 0.f;
    float mst[2] = {-1e30f, -1e30f};
    float lst[2] = {0.f, 0.f};

    const int mat = lid >> 3;
    const int wi = lid & 7;

    for (int t = 0; t < ntiles; t++) {
        const uint32_t st = sb + SM_STG + (t & 1) * STGSZ;

        // ---- S = (Qh + Ql) K^T : 2 passes over 128x128 tile ----
        float sacc[16][4];
#pragma unroll
        for (int i = 0; i < 16; i++)
#pragma unroll
            for (int q = 0; q < 4; q++) sacc[i][q] = 0.f;

#pragma unroll
        for (int pass = 0; pass < 2; pass++) {
            const uint32_t qb = sb + (pass ? SMQ_LO : SMQ_HI);
            const uint32_t kb = st + SK_OFF;
#pragma unroll
            for (int kk = 0; kk < 8; kk++) {
                uint32_t a[4];
                {
                    int r = wm + (lid & 15);
                    int c16 = 2 * kk + (lid >> 4);
                    LDMATRIX_X4(a[0], a[1], a[2], a[3],
                                qb + r * 256 + ((c16 ^ (r & 7)) << 4));
                }
                uint32_t bf[16][2];
#pragma unroll
                for (int jj = 0; jj < 8; jj++) {
                    int r = jj * 16 + (mat >> 1) * 8 + wi;
                    int c16 = 2 * kk + (mat & 1);
                    LDMATRIX_X4(bf[2 * jj][0], bf[2 * jj][1],
                                bf[2 * jj + 1][0], bf[2 * jj + 1][1],
                                kb + r * 256 + ((c16 ^ (r & 7)) << 4));
                }
#pragma unroll
                for (int nb = 0; nb < 16; nb++)
                    MMA_F16(sacc[nb], a, bf[nb]);
            }
        }

        // ---- online softmax (log2 domain) ----
        const bool dg = (t == qt);
#pragma unroll
        for (int hf = 0; hf < 2; hf++) {
            const int row = m0 + wm + g + hf * 8;
            float tm = -1e30f;
#pragma unroll
            for (int nb = 0; nb < 16; nb++) {
#pragma unroll
                for (int e = 0; e < 2; e++) {
                    float s = sacc[nb][2 * hf + e] * SOFTMAX_SCALE_LOG2;
                    if (dg && (t * FN + nb * 8 + tq * 2 + e > row)) s = -1e30f;
                    sacc[nb][2 * hf + e] = s;
                    tm = fmaxf(tm, s);
                }
            }
            tm = fmaxf(tm, __shfl_xor_sync(0xffffffffu, tm, 1));
            tm = fmaxf(tm, __shfl_xor_sync(0xffffffffu, tm, 2));
            float mn = fmaxf(mst[hf], tm);
            float corr = exp2f(mst[hf] - mn);
            mst[hf] = mn;
            float sum = 0.f;
#pragma unroll
            for (int nb = 0; nb < 16; nb++) {
#pragma unroll
                for (int e = 0; e < 2; e++) {
                    float p = exp2f(sacc[nb][2 * hf + e] - mn);
                    sacc[nb][2 * hf + e] = p;
                    sum += p;
                }
            }
            sum += __shfl_xor_sync(0xffffffffu, sum, 1);
            sum += __shfl_xor_sync(0xffffffffu, sum, 2);
            lst[hf] = lst[hf] * corr + sum;
#pragma unroll
            for (int nb = 0; nb < 16; nb++) {
                oacc[nb][2 * hf + 0] *= corr;
                oacc[nb][2 * hf + 1] *= corr;
            }
        }

        // ---- O += (Ph + Pl) Vh, P packed per-kk on the fly ----
#pragma unroll
        for (int kk = 0; kk < 8; kk++) {
            uint32_t ah[4], al[4];
            split2h(sacc[2 * kk][0], sacc[2 * kk][1], ah[0], al[0]);
            split2h(sacc[2 * kk][2], sacc[2 * kk][3], ah[1], al[1]);
            split2h(sacc[2 * kk + 1][0], sacc[2 * kk + 1][1], ah[2], al[2]);
            split2h(sacc[2 * kk + 1][2], sacc[2 * kk + 1][3], ah[3], al[3]);
#pragma unroll
            for (int jj = 0; jj < 8; jj++) {
                int r = jj * 16 + (mat >> 1) * 8 + wi;
                int c16 = 2 * kk + (mat & 1);
                uint32_t v[4];
                LDMATRIX_X4(v[0], v[1], v[2], v[3],
                            st + SV_OFF + r * 256 + ((c16 ^ (r & 7)) << 4));
                MMA_F16(oacc[2 * jj], ah, v);
                MMA_F16(oacc[2 * jj + 1], ah, (v + 2));
                MMA_F16(oacc[2 * jj], al, v);
                MMA_F16(oacc[2 * jj + 1], al, (v + 2));
            }
        }

        __syncthreads();
        if (t + 2 < ntiles) issueKV(t + 2, t & 1);
        CP_COMMIT();
        if (t + 1 < ntiles) {
            CP_WAIT1();
        } else {
            CP_WAIT0();
        }
        __syncthreads();
    }

    // ---- epilogue: O/l -> fp16 hi/lo into gA ----
#pragma unroll
    for (int hf = 0; hf < 2; hf++) {
        float inv = 1.f / lst[hf];
        size_t row = bS + m0 + wm + g + hf * 8;
#pragma unroll
        for (int nb = 0; nb < 16; nb++) {
            float v0 = oacc[nb][2 * hf] * inv;
            float v1 = oacc[nb][2 * hf + 1] * inv;
            uint32_t hh, ll;
            split2h(v0, v1, hh, ll);
            size_t off = row * HID_C + h * HEAD_D + nb * 8 + tq * 2;
            *(uint32_t*)&gA_hi[off] = hh;
            *(uint32_t*)&gA_lo[off] = ll;
        }
    }
}

// ---------------------------------------------------------------------------
extern "C" void kernel_launch(void* const* d_in, const int* in_sizes, int n_in,
                              void* d_out, int out_size)
{
    (void)in_sizes; (void)n_in; (void)out_size;
    const float* hs  = (const float*)d_in[0];
    /* d_in[1] = attention_mask (exact causal tril) applied analytically */
    const float* Wq  = (const float*)d_in[2];
    const float* bq  = (const float*)d_in[3];
    const float* Wkv = (const float*)d_in[4];
    const float* bkv = (const float*)d_in[5];
    const float* Wp  = (const float*)d_in[6];
    const float* bp  = (const float*)d_in[7];
    float* out = (float*)d_out;

    __half *pAhi, *pAlo, *pWqh, *pWkh, *pWph;
    cudaGetSymbolAddress((void**)&pAhi, gA_hi);
    cudaGetSymbolAddress((void**)&pAlo, gA_lo);
    cudaGetSymbolAddress((void**)&pWqh, gWq_hi);
    cudaGetSymbolAddress((void**)&pWkh, gWkv_hi);
    cudaGetSymbolAddress((void**)&pWph, gWp_hi);

    cudaFuncSetAttribute(mma_gemm_kernel,
                         cudaFuncAttributeMaxDynamicSharedMemorySize, GEMM_SMEM);
    cudaFuncSetAttribute(flash_mma_kernel,
                         cudaFuncAttributeMaxDynamicSharedMemorySize, FA_SMEM);

    // 1. split hidden states into fp16 hi/lo
    {
        int n4 = M_ROWS * HID_C / 4;
        split_f32_kernel<<<(n4 + 255) / 256, 256>>>(hs, pAhi, pAlo, n4);
    }
    // 2. fused transpose+convert of all three weights
    tconv_all_kernel<<<dim3(HID_C / 32, HID_C / 32, 3), dim3(32, 8)>>>(Wq, Wp, Wkv);

    // 3. fused Q + KV projection (grid.x: 16 Q blocks + 2 KV blocks)
    mma_gemm_kernel<<<dim3(18, M_ROWS / BM), 256, GEMM_SMEM>>>(
        pAhi, pAlo, pWqh, bq, pWkh, bkv, nullptr, HID_C, 1);
    // 4. attention -> gA_hi/gA_lo
    flash_mma_kernel<<<dim3(S_LEN / FM, N_HEADS, B_SZ), 256, FA_SMEM>>>();
    // 5. out = attn @ Wp + bp
    mma_gemm_kernel<<<dim3(16, M_ROWS / BM), 256, GEMM_SMEM>>>(
        pAhi, pAlo, pWph, bp, nullptr, nullptr, out, HID_C, 0);
}